// round 15
// baseline (speedup 1.0000x reference)
#include <cuda_runtime.h>
#include <cuda_bf16.h>
#include <math.h>

#define HW 50176              // 224*224
#define L_TOK 401408          // 8*224*224
#define NWIN 8192

// Scratch
__device__ __nv_bfloat16 g_qkv[(size_t)L_TOK * 288];
__device__ __nv_bfloat16 g_ctx[(size_t)L_TOK * 96];
// bf16 weights
__device__ __nv_bfloat16 g_bwq[288 * 96];
__device__ __nv_bfloat16 g_bwp[96 * 96];
__device__ __nv_bfloat16 g_bw1[384 * 96];
__device__ __nv_bfloat16 g_bw2[96 * 384];
// combined rel-pos bias + shift-mask tables, 4 classes, [49][50] bf16
__device__ __nv_bfloat16 g_tbl[4 * 2456];

// ---- helpers --------------------------------------------------------------
__device__ __forceinline__ unsigned bf2u(float a, float b) {
    __nv_bfloat162 h = __floats2bfloat162_rn(a, b);
    return *reinterpret_cast<unsigned*>(&h);
}
__device__ __forceinline__ void mma16(float* c, const unsigned* a,
                                      unsigned b0, unsigned b1) {
    asm("mma.sync.aligned.m16n8k16.row.col.f32.bf16.bf16.f32 "
        "{%0,%1,%2,%3}, {%4,%5,%6,%7}, {%8,%9}, {%0,%1,%2,%3};"
        : "+f"(c[0]), "+f"(c[1]), "+f"(c[2]), "+f"(c[3])
        : "r"(a[0]), "r"(a[1]), "r"(a[2]), "r"(a[3]), "r"(b0), "r"(b1));
}
__device__ __forceinline__ unsigned s2u(const void* p) {
    return (unsigned)__cvta_generic_to_shared(p);
}
__device__ __forceinline__ void cp16(unsigned dst, const void* src) {
    asm volatile("cp.async.cg.shared.global [%0], [%1], 16;" :: "r"(dst), "l"(src));
}
#define CP_COMMIT() asm volatile("cp.async.commit_group;")
#define CP_WAIT0()  asm volatile("cp.async.wait_group 0;")
#define CP_WAIT1()  asm volatile("cp.async.wait_group 1;")

__device__ __forceinline__ void ldsm_x4(unsigned& r0, unsigned& r1,
                                        unsigned& r2, unsigned& r3, unsigned addr) {
    asm volatile("ldmatrix.sync.aligned.m8n8.x4.shared.b16 {%0,%1,%2,%3}, [%4];"
                 : "=r"(r0), "=r"(r1), "=r"(r2), "=r"(r3) : "r"(addr));
}
__device__ __forceinline__ void ldsm_x2(unsigned& r0, unsigned& r1, unsigned addr) {
    asm volatile("ldmatrix.sync.aligned.m8n8.x2.shared.b16 {%0,%1}, [%2];"
                 : "=r"(r0), "=r"(r1) : "r"(addr));
}
__device__ __forceinline__ void ldsm_x2t(unsigned& r0, unsigned& r1, unsigned addr) {
    asm volatile("ldmatrix.sync.aligned.m8n8.x2.trans.shared.b16 {%0,%1}, [%2];"
                 : "=r"(r0), "=r"(r1) : "r"(addr));
}
__device__ __forceinline__ void lda_frag(unsigned* a, unsigned baseB, int r0,
                                         int ksB, int strideB, int lane) {
    unsigned addr = baseB + (unsigned)((r0 + (lane & 15)) * strideB + ksB + (lane >> 4) * 16);
    ldsm_x4(a[0], a[1], a[2], a[3], addr);
}
__device__ __forceinline__ void ldb_frag(unsigned& b0, unsigned& b1, unsigned baseB,
                                         int cb, int ksB, int strideB, int lane) {
    unsigned addr = baseB + (unsigned)((cb + (lane & 7)) * strideB + ksB + ((lane >> 3) & 1) * 16);
    ldsm_x2(b0, b1, addr);
}
// fast GELU: 0.5x(1+tanh(0.79788456x + 0.03567741x^3)) with tanh.approx
__device__ __forceinline__ float gelu_f(float x) {
    float x2 = x * x;
    float z = x * (0.7978845608028654f + 0.0356774081f * x2);
    float t;
    asm("tanh.approx.f32 %0, %1;" : "=f"(t) : "f"(z));
    return 0.5f * x * (1.0f + t);
}

// ---------------------------------------------------------------------------
// Kernel 0: weights fp32 -> bf16 AND bias+mask class tables (merged)
// ---------------------------------------------------------------------------
__global__ __launch_bounds__(256) void k_prep(const float* __restrict__ qkvw,
                                              const float* __restrict__ pw,
                                              const float* __restrict__ w1,
                                              const float* __restrict__ w2,
                                              const float* __restrict__ rel) {
    int b = blockIdx.x;
    if (b < 432) {
        int i = b * 256 + threadIdx.x;
        if (i < 27648)       g_bwq[i] = __float2bfloat16(qkvw[i]);
        else if (i < 36864)  g_bwp[i - 27648] = __float2bfloat16(pw[i - 27648]);
        else if (i < 73728)  g_bw1[i - 36864] = __float2bfloat16(w1[i - 36864]);
        else                 g_bw2[i - 73728] = __float2bfloat16(w2[i - 73728]);
    } else {
        int cls = b - 432;
        int re = cls >> 1, ce = cls & 1;
        for (int e = threadIdx.x; e < 2456; e += 256) {
            int i = e / 50, j = e % 50;
            float v = 0.f;
            if (i < 49 && j < 49) {
                int idx = (i / 7 - j / 7 + 6) * 13 + (i % 7 - j % 7 + 6);
                v = rel[idx];
                int li = (re ? ((i / 7) < 4 ? 1 : 2) : 0) * 3 + (ce ? ((i % 7) < 4 ? 1 : 2) : 0);
                int lj = (re ? ((j / 7) < 4 ? 1 : 2) : 0) * 3 + (ce ? ((j % 7) < 4 ? 1 : 2) : 0);
                if (li != lj) v -= 100.f;
            }
            g_tbl[cls * 2456 + e] = __float2bfloat16(v);
        }
    }
}

// ---------------------------------------------------------------------------
// Kernel 1: fused NCHW load + LN1 + QKV GEMM.  BM=64. (frozen from R14)
// ---------------------------------------------------------------------------
#define QKV_XS 0
#define QKV_AS 6528
#define QKV_W0 9856
#define QKV_SMEM_U 14848

__global__ __launch_bounds__(256) void k_qkv(const float* __restrict__ x,
                                             const float* __restrict__ lnw,
                                             const float* __restrict__ lnb,
                                             const float* __restrict__ bias) {
    extern __shared__ unsigned smem_u[];
    int tid = threadIdx.x;
    int lane = tid & 31, warp = tid >> 5;
    int warp_m = warp & 1, warp_n = warp >> 1;
    int g = lane >> 2, tig = lane & 3;
    int m0 = blockIdx.x * 64;
    int bb = m0 / HW, hw0 = m0 % HW;

    unsigned sbase = s2u(smem_u);
#pragma unroll
    for (int l = 0; l < 6; ++l) {
        int o = tid + l * 256;
        int ch = o >> 4, t4 = o & 15;
        cp16(sbase + (QKV_XS + ch * 68 + t4 * 4) * 4,
             x + ((size_t)bb * 96 + ch) * HW + hw0 + t4 * 4);
    }
#pragma unroll
    for (int l = 0; l < 5; ++l) {
        int o = tid + l * 256;
        if (o < 1152) {
            int row = o / 12, ch = o % 12;
            cp16(sbase + QKV_W0 * 4 + row * 208 + ch * 16, g_bwq + (size_t)row * 96 + ch * 8);
        }
    }
    CP_COMMIT();
    CP_WAIT0();
    __syncthreads();

    {
        const float* xs = reinterpret_cast<const float*>(smem_u + QKV_XS);
        int r = tid >> 2, quarter = tid & 3;
        float vals[24];
        float s = 0.f, q = 0.f;
#pragma unroll
        for (int i = 0; i < 24; ++i) {
            float v = xs[(quarter * 24 + i) * 68 + r];
            vals[i] = v;
            s += v; q += v * v;
        }
        s += __shfl_xor_sync(0xffffffffu, s, 1);
        q += __shfl_xor_sync(0xffffffffu, q, 1);
        s += __shfl_xor_sync(0xffffffffu, s, 2);
        q += __shfl_xor_sync(0xffffffffu, q, 2);
        float mean = s * (1.f / 96.f);
        float var = q * (1.f / 96.f) - mean * mean;
        float rstd = rsqrtf(var + 1e-5f);
        unsigned* As = smem_u + QKV_AS;
#pragma unroll
        for (int i = 0; i < 12; ++i) {
            int c = quarter * 24 + i * 2;
            As[r * 52 + c / 2] = bf2u((vals[i * 2] - mean) * rstd * lnw[c] + lnb[c],
                                      (vals[i * 2 + 1] - mean) * rstd * lnw[c + 1] + lnb[c + 1]);
        }
    }
    __syncthreads();

#pragma unroll
    for (int l = 0; l < 5; ++l) {
        int o = tid + l * 256;
        if (o < 1152) {
            int row = o / 12, ch = o % 12;
            cp16(sbase + 0 + row * 208 + ch * 16, g_bwq + (size_t)(96 + row) * 96 + ch * 8);
        }
    }
    CP_COMMIT();

    unsigned aBase = sbase + QKV_AS * 4;
    __nv_bfloat16* out = g_qkv;

    auto gemm_block = [&](unsigned bBase, int nb) {
        float acc[2][3][4];
#pragma unroll
        for (int mt = 0; mt < 2; ++mt)
#pragma unroll
            for (int nt = 0; nt < 3; ++nt)
#pragma unroll
                for (int q = 0; q < 4; ++q) acc[mt][nt][q] = 0.f;
#pragma unroll
        for (int ks = 0; ks < 6; ++ks) {
            unsigned a[2][4];
#pragma unroll
            for (int mt = 0; mt < 2; ++mt)
                lda_frag(a[mt], aBase, warp_m * 32 + mt * 16, ks * 32, 208, lane);
#pragma unroll
            for (int nt = 0; nt < 3; ++nt) {
                unsigned b0, b1;
                ldb_frag(b0, b1, bBase, warp_n * 24 + nt * 8, ks * 32, 208, lane);
#pragma unroll
                for (int mt = 0; mt < 2; ++mt)
                    mma16(acc[mt][nt], a[mt], b0, b1);
            }
        }
        float sc = (nb == 0) ? 0.10206207261596575f : 1.0f;
#pragma unroll
        for (int mt = 0; mt < 2; ++mt) {
            int r0 = m0 + warp_m * 32 + mt * 16 + g;
#pragma unroll
            for (int nt = 0; nt < 3; ++nt) {
                int col = nb * 96 + warp_n * 24 + nt * 8 + 2 * tig;
                float bi0 = bias[col], bi1 = bias[col + 1];
                *reinterpret_cast<unsigned*>(&out[(size_t)r0 * 288 + col]) =
                    bf2u((acc[mt][nt][0] + bi0) * sc, (acc[mt][nt][1] + bi1) * sc);
                *reinterpret_cast<unsigned*>(&out[(size_t)(r0 + 8) * 288 + col]) =
                    bf2u((acc[mt][nt][2] + bi0) * sc, (acc[mt][nt][3] + bi1) * sc);
            }
        }
    };

    gemm_block(sbase + QKV_W0 * 4, 0);
    __syncthreads();
#pragma unroll
    for (int l = 0; l < 5; ++l) {
        int o = tid + l * 256;
        if (o < 1152) {
            int row = o / 12, ch = o % 12;
            cp16(sbase + QKV_W0 * 4 + row * 208 + ch * 16,
                 g_bwq + (size_t)(192 + row) * 96 + ch * 8);
        }
    }
    CP_COMMIT();
    CP_WAIT1();
    __syncthreads();
    gemm_block(sbase + 0, 1);
    CP_WAIT0();
    __syncthreads();
    gemm_block(sbase + QKV_W0 * 4, 2);
}

// ---------------------------------------------------------------------------
// Fused proj + x-residual + LN2 + MLP1 + GELU + MLP2 + residual + NCHW out.
// BM=128, 512 threads (16 warps: 4(M) x 4(N)), 1 CTA/SM.
// smem (u32): A@0 (6656), S0@6656, S1@11648 (4992 ea), M/XR@16640 (25088),
//             EX@41728 (1024). Total 42752u = 171008B.
// ---------------------------------------------------------------------------
#define PML_S0 6656
#define PML_S1 11648
#define PML_M  16640
#define PML_EX 41728
#define PML_SMEM_U 42752

__global__ __launch_bounds__(512) void k_pml(const __nv_bfloat16* __restrict__ A,
                                             const float* __restrict__ pbias,
                                             const float* __restrict__ x,
                                             const float* __restrict__ lnw,
                                             const float* __restrict__ lnb,
                                             const float* __restrict__ b1,
                                             const float* __restrict__ b2,
                                             float* __restrict__ out) {
    extern __shared__ unsigned smem_u[];
    int tid = threadIdx.x;
    int lane = tid & 31, warp = tid >> 5;
    int warp_m = warp & 3, warp_n = warp >> 2;
    int g = lane >> 2, tig = lane & 3;
    int m0 = blockIdx.x * 128;
    int bb = m0 / HW, hw0 = m0 % HW;

    unsigned sbase = s2u(smem_u);
    // G1: ctx A-tile (128x12 chunks) + proj W -> S0
#pragma unroll
    for (int l = 0; l < 3; ++l) {
        int o = tid + l * 512;
        int row = o / 12, ch = o % 12;
        cp16(sbase + row * 208 + ch * 16, A + (size_t)(m0 + row) * 96 + ch * 8);
    }
#pragma unroll
    for (int l = 0; l < 3; ++l) {
        int o = tid + l * 512;
        if (o < 1152) {
            int row = o / 12, ch = o % 12;
            cp16(sbase + PML_S0 * 4 + row * 208 + ch * 16, g_bwp + (size_t)row * 96 + ch * 8);
        }
    }
    CP_COMMIT();
    // G2: W1 block 0 -> S1, x residual tile (96 ch x 128 tok) -> XR on M
#pragma unroll
    for (int l = 0; l < 3; ++l) {
        int o = tid + l * 512;
        if (o < 1152) {
            int row = o / 12, ch = o % 12;
            cp16(sbase + PML_S1 * 4 + row * 208 + ch * 16, g_bw1 + (size_t)row * 96 + ch * 8);
        }
    }
#pragma unroll
    for (int l = 0; l < 6; ++l) {
        int o = tid + l * 512;
        int ch = o >> 5, t4 = o & 31;
        cp16(sbase + (PML_M + ch * 132 + t4 * 4) * 4,
             x + ((size_t)bb * 96 + ch) * HW + hw0 + t4 * 4);
    }
    CP_COMMIT();
    CP_WAIT1();
    __syncthreads();

    // ---- proj GEMM -> h ----------------------------------------------------
    float h[2][3][4];
#pragma unroll
    for (int mt = 0; mt < 2; ++mt)
#pragma unroll
        for (int nt = 0; nt < 3; ++nt)
#pragma unroll
            for (int q = 0; q < 4; ++q) h[mt][nt][q] = 0.f;
#pragma unroll
    for (int ks = 0; ks < 6; ++ks) {
        unsigned a[2][4];
#pragma unroll
        for (int mt = 0; mt < 2; ++mt)
            lda_frag(a[mt], sbase, warp_m * 32 + mt * 16, ks * 32, 208, lane);
#pragma unroll
        for (int nt = 0; nt < 3; ++nt) {
            unsigned b0, b1;
            ldb_frag(b0, b1, sbase + PML_S0 * 4, warp_n * 24 + nt * 8, ks * 32, 208, lane);
#pragma unroll
            for (int mt = 0; mt < 2; ++mt)
                mma16(h[mt][nt], a[mt], b0, b1);
        }
    }
    CP_WAIT0();        // XR (and W1b0) ready
    __syncthreads();
    // epilogue: + proj bias + x residual from XR smem
    {
        const float* xr = reinterpret_cast<const float*>(smem_u + PML_M);
#pragma unroll
        for (int mt = 0; mt < 2; ++mt) {
            int r0 = warp_m * 32 + mt * 16 + g;
#pragma unroll
            for (int nt = 0; nt < 3; ++nt) {
                int col = warp_n * 24 + nt * 8 + 2 * tig;
                h[mt][nt][0] += pbias[col]     + xr[col * 132 + r0];
                h[mt][nt][1] += pbias[col + 1] + xr[(col + 1) * 132 + r0];
                h[mt][nt][2] += pbias[col]     + xr[col * 132 + r0 + 8];
                h[mt][nt][3] += pbias[col + 1] + xr[(col + 1) * 132 + r0 + 8];
            }
        }
    }
    // ---- LN2: register partials + smem exchange ---------------------------
    float ps[2][2], pq[2][2];
#pragma unroll
    for (int mt = 0; mt < 2; ++mt)
#pragma unroll
        for (int rr = 0; rr < 2; ++rr) {
            float s = 0.f, q = 0.f;
#pragma unroll
            for (int nt = 0; nt < 3; ++nt) {
                s += h[mt][nt][rr * 2 + 0] + h[mt][nt][rr * 2 + 1];
                q += h[mt][nt][rr * 2 + 0] * h[mt][nt][rr * 2 + 0] +
                     h[mt][nt][rr * 2 + 1] * h[mt][nt][rr * 2 + 1];
            }
            s += __shfl_xor_sync(0xffffffffu, s, 1);
            q += __shfl_xor_sync(0xffffffffu, q, 1);
            s += __shfl_xor_sync(0xffffffffu, s, 2);
            q += __shfl_xor_sync(0xffffffffu, q, 2);
            ps[mt][rr] = s; pq[mt][rr] = q;
        }
    __syncthreads();   // XR reads done
    {
        float2* ex = reinterpret_cast<float2*>(smem_u + PML_EX);
        if (tig == 0) {
#pragma unroll
            for (int mt = 0; mt < 2; ++mt)
#pragma unroll
                for (int rr = 0; rr < 2; ++rr) {
                    int row = warp_m * 32 + mt * 16 + g + rr * 8;
                    ex[row * 4 + warp_n] = make_float2(ps[mt][rr], pq[mt][rr]);
                }
        }
    }
    __syncthreads();
    {
        const float2* ex = reinterpret_cast<const float2*>(smem_u + PML_EX);
        unsigned* As = smem_u;   // ln2 bf16 tile overlays ctx
#pragma unroll
        for (int mt = 0; mt < 2; ++mt)
#pragma unroll
            for (int rr = 0; rr < 2; ++rr) {
                int row = warp_m * 32 + mt * 16 + g + rr * 8;
                float2 e0 = ex[row * 4 + 0], e1 = ex[row * 4 + 1];
                float2 e2 = ex[row * 4 + 2], e3 = ex[row * 4 + 3];
                float s = e0.x + e1.x + e2.x + e3.x;
                float q = e0.y + e1.y + e2.y + e3.y;
                float mean = s * (1.f / 96.f);
                float var = q * (1.f / 96.f) - mean * mean;
                float rstd = rsqrtf(var + 1e-5f);
#pragma unroll
                for (int nt = 0; nt < 3; ++nt) {
                    int col = warp_n * 24 + nt * 8 + 2 * tig;
                    float v0 = (h[mt][nt][rr * 2 + 0] - mean) * rstd * lnw[col] + lnb[col];
                    float v1 = (h[mt][nt][rr * 2 + 1] - mean) * rstd * lnw[col + 1] + lnb[col + 1];
                    As[row * 52 + col / 2] = bf2u(v0, v1);
                }
            }
    }
    __syncthreads();

    unsigned* MU = smem_u + PML_M;
    const unsigned wslot[2] = {PML_S1, PML_S0};

    // ---- MLP1: 4 N-blocks + GELU -> M smem --------------------------------
    for (int nb = 0; nb < 4; ++nb) {
        CP_WAIT0();
        __syncthreads();
        {
            const __nv_bfloat16* nsrc = (nb < 3)
                ? g_bw1 + (size_t)(nb + 1) * 96 * 96
                : g_bw2;
            unsigned dslot = wslot[(nb + 1) & 1];
#pragma unroll
            for (int l = 0; l < 3; ++l) {
                int o = tid + l * 512;
                if (o < 1152) {
                    int row = o / 12, ch = o % 12;
                    if (nb < 3)
                        cp16(sbase + dslot * 4 + row * 208 + ch * 16, nsrc + (size_t)row * 96 + ch * 8);
                    else
                        cp16(sbase + dslot * 4 + row * 208 + ch * 16, nsrc + (size_t)row * 384 + ch * 8);
                }
            }
            CP_COMMIT();
        }
        unsigned bBase = sbase + wslot[nb & 1] * 4;
        float acc[2][3][4];
#pragma unroll
        for (int mt = 0; mt < 2; ++mt)
#pragma unroll
            for (int nt = 0; nt < 3; ++nt)
#pragma unroll
                for (int q = 0; q < 4; ++q) acc[mt][nt][q] = 0.f;
#pragma unroll
        for (int ks = 0; ks < 6; ++ks) {
            unsigned a[2][4];
#pragma unroll
            for (int mt = 0; mt < 2; ++mt)
                lda_frag(a[mt], sbase, warp_m * 32 + mt * 16, ks * 32, 208, lane);
#pragma unroll
            for (int nt = 0; nt < 3; ++nt) {
                unsigned b0, b1;
                ldb_frag(b0, b1, bBase, warp_n * 24 + nt * 8, ks * 32, 208, lane);
#pragma unroll
                for (int mt = 0; mt < 2; ++mt)
                    mma16(acc[mt][nt], a[mt], b0, b1);
            }
        }
#pragma unroll
        for (int mt = 0; mt < 2; ++mt) {
            int r0 = warp_m * 32 + mt * 16 + g;
#pragma unroll
            for (int nt = 0; nt < 3; ++nt) {
                int col = warp_n * 24 + nt * 8 + 2 * tig;
                float bi0 = b1[nb * 96 + col], bi1 = b1[nb * 96 + col + 1];
                float v0 = gelu_f(acc[mt][nt][0] + bi0);
                float v1 = gelu_f(acc[mt][nt][1] + bi1);
                float v2 = gelu_f(acc[mt][nt][2] + bi0);
                float v3 = gelu_f(acc[mt][nt][3] + bi1);
                MU[r0 * 196 + nb * 48 + col / 2] = bf2u(v0, v1);
                MU[(r0 + 8) * 196 + nb * 48 + col / 2] = bf2u(v2, v3);
            }
        }
    }

    // ---- MLP2: 4 K-chunks, accumulate into h -------------------------------
    for (int kc = 0; kc < 4; ++kc) {
        CP_WAIT0();
        __syncthreads();
        if (kc < 3) {
            unsigned dslot = wslot[(kc + 1) & 1];
#pragma unroll
            for (int l = 0; l < 3; ++l) {
                int o = tid + l * 512;
                if (o < 1152) {
                    int row = o / 12, ch = o % 12;
                    cp16(sbase + dslot * 4 + row * 208 + ch * 16,
                         g_bw2 + (size_t)row * 384 + (kc + 1) * 96 + ch * 8);
                }
            }
            CP_COMMIT();
        }
        unsigned bBase = sbase + wslot[kc & 1] * 4;
        unsigned mBase = sbase + PML_M * 4 + kc * 192;
#pragma unroll
        for (int ks = 0; ks < 6; ++ks) {
            unsigned a[2][4];
#pragma unroll
            for (int mt = 0; mt < 2; ++mt)
                lda_frag(a[mt], mBase, warp_m * 32 + mt * 16, ks * 32, 784, lane);
#pragma unroll
            for (int nt = 0; nt < 3; ++nt) {
                unsigned b0, b1;
                ldb_frag(b0, b1, bBase, warp_n * 24 + nt * 8, ks * 32, 208, lane);
#pragma unroll
                for (int mt = 0; mt < 2; ++mt)
                    mma16(h[mt][nt], a[mt], b0, b1);
            }
        }
    }

    // ---- epilogue: +b2, NCHW store -----------------------------------------
    __syncthreads();
    float (*st)[98] = reinterpret_cast<float (*)[98]>(smem_u + PML_M);
#pragma unroll
    for (int mt = 0; mt < 2; ++mt) {
        int lr0 = warp_m * 32 + mt * 16 + g;
#pragma unroll
        for (int nt = 0; nt < 3; ++nt) {
            int col = warp_n * 24 + nt * 8 + 2 * tig;
            float bi0 = b2[col], bi1 = b2[col + 1];
            *reinterpret_cast<float2*>(&st[lr0][col]) =
                make_float2(h[mt][nt][0] + bi0, h[mt][nt][1] + bi1);
            *reinterpret_cast<float2*>(&st[lr0 + 8][col]) =
                make_float2(h[mt][nt][2] + bi0, h[mt][nt][3] + bi1);
        }
    }
    __syncthreads();
    float* ob = out + (size_t)bb * 96 * HW + hw0;
#pragma unroll
    for (int l = 0; l < 24; ++l) {
        int e = tid + l * 512;
        int ch = e >> 7, tok = e & 127;
        ob[(size_t)ch * HW + tok] = st[tok][ch];
    }
}

// ---------------------------------------------------------------------------
// Attention, register softmax; Q arrives pre-scaled. (frozen)
// ---------------------------------------------------------------------------
#define QS_U 0
#define KS_U 3328
#define VS_U 6656
#define TB_U 9984
#define EX_U 3328
#define SM_ATTN_U 11212

__global__ __launch_bounds__(256) void k_attn() {
    extern __shared__ unsigned smem_u[];
    __shared__ int tok_s[49];

    int win = blockIdx.x;
    int bb = win >> 10;
    int wr = (win >> 5) & 31;
    int wc = win & 31;
    int tid = threadIdx.x;
    int lane = tid & 31, warp = tid >> 5;
    int g = lane >> 2, tig = lane & 3;
    int mt = warp & 3, nhalf = warp >> 2;
    int cls = ((wr == 31) ? 2 : 0) + ((wc == 31) ? 1 : 0);

    if (tid < 49) {
        int i = tid / 7, j = tid % 7;
        int sr = wr * 7 + i, sc = wc * 7 + j;
        int r = sr + 3; if (r >= 224) r -= 224;
        int c = sc + 3; if (c >= 224) c -= 224;
        tok_s[tid] = bb * HW + r * 224 + c;
    }
    for (int e = tid; e < 780; e += 256) smem_u[VS_U + 49 * 52 + e] = 0u;
    __syncthreads();

    unsigned sbase = s2u(smem_u);
#pragma unroll
    for (int l = 0; l < 7; ++l) {
        int e = tid + l * 256;
        if (e < 1764) {
            int third = e / 588;
            int ee = e - third * 588;
            int row = ee / 12, ch = ee % 12;
            cp16(sbase + third * 13312 + row * 208 + ch * 16,
                 g_qkv + (size_t)tok_s[row] * 288 + third * 96 + ch * 8);
        }
    }
    {
        const __nv_bfloat16* tsrc = g_tbl + cls * 2456;
        for (int o = tid; o < 307; o += 256)
            cp16(sbase + TB_U * 4 + o * 16, tsrc + o * 8);
    }
    CP_COMMIT();
    CP_WAIT0();
    __syncthreads();

    float acc[4][4];
#pragma unroll
    for (int t = 0; t < 4; ++t)
#pragma unroll
        for (int q = 0; q < 4; ++q) acc[t][q] = 0.f;
#pragma unroll
    for (int ks = 0; ks < 6; ++ks) {
        unsigned a[4];
        lda_frag(a, sbase, mt * 16, ks * 32, 208, lane);
#pragma unroll
        for (int t = 0; t < 4; ++t) {
            unsigned b0, b1;
            ldb_frag(b0, b1, sbase + KS_U * 4, (nhalf * 4 + t) * 8, ks * 32, 208, lane);
            mma16(acc[t], a, b0, b1);
        }
    }

    const __nv_bfloat16* tb = reinterpret_cast<const __nv_bfloat16*>(smem_u + TB_U);
    float mx[2] = {-1e30f, -1e30f};
#pragma unroll
    for (int t = 0; t < 4; ++t) {
        int j0 = (nhalf * 4 + t) * 8 + 2 * tig;
#pragma unroll
        for (int rr = 0; rr < 2; ++rr) {
            int i = mt * 16 + g + rr * 8;
            float v0 = acc[t][rr * 2 + 0];
            float v1 = acc[t][rr * 2 + 1];
            if (i < 49 && j0 < 49) {
                __nv_bfloat162 t2 = *reinterpret_cast<const __nv_bfloat162*>(&tb[i * 50 + j0]);
                v0 += __bfloat162float(t2.x);
                v1 += __bfloat162float(t2.y);
            }
            if (j0 > 48) v0 = -1e30f;
            if (j0 + 1 > 48) v1 = -1e30f;
            acc[t][rr * 2 + 0] = v0;
            acc[t][rr * 2 + 1] = v1;
            mx[rr] = fmaxf(mx[rr], fmaxf(v0, v1));
        }
    }
#pragma unroll
    for (int rr = 0; rr < 2; ++rr) {
        mx[rr] = fmaxf(mx[rr], __shfl_xor_sync(0xffffffffu, mx[rr], 1));
        mx[rr] = fmaxf(mx[rr], __shfl_xor_sync(0xffffffffu, mx[rr], 2));
    }
    float sm[2] = {0.f, 0.f};
#pragma unroll
    for (int t = 0; t < 4; ++t)
#pragma unroll
        for (int rr = 0; rr < 2; ++rr) {
            float p0 = __expf(acc[t][rr * 2 + 0] - mx[rr]);
            float p1 = __expf(acc[t][rr * 2 + 1] - mx[rr]);
            acc[t][rr * 2 + 0] = p0;
            acc[t][rr * 2 + 1] = p1;
            sm[rr] += p0 + p1;
        }
#pragma unroll
    for (int rr = 0; rr < 2; ++rr) {
        sm[rr] += __shfl_xor_sync(0xffffffffu, sm[rr], 1);
        sm[rr] += __shfl_xor_sync(0xffffffffu, sm[rr], 2);
    }

    __syncthreads();
    {
        float2* ex = reinterpret_cast<float2*>(smem_u + EX_U);
        if (tig == 0) {
#pragma unroll
            for (int rr = 0; rr < 2; ++rr) {
                int i = mt * 16 + g + rr * 8;
                ex[i * 2 + nhalf] = make_float2(mx[rr], sm[rr]);
            }
        }
    }
    __syncthreads();
    {
        const float2* ex = reinterpret_cast<const float2*>(smem_u + EX_U);
        __nv_bfloat16* atth = reinterpret_cast<__nv_bfloat16*>(smem_u + QS_U);
#pragma unroll
        for (int rr = 0; rr < 2; ++rr) {
            int i = mt * 16 + g + rr * 8;
            float2 e0 = ex[i * 2 + 0];
            float2 e1 = ex[i * 2 + 1];
            float M = fmaxf(e0.x, e1.x);
            float S = e0.y * __expf(e0.x - M) + e1.y * __expf(e1.x - M);
            float f = __expf(mx[rr] - M) / S;
#pragma unroll
            for (int t = 0; t < 4; ++t) {
                unsigned* dst = reinterpret_cast<unsigned*>(atth) +
                                i * 36 + (nhalf * 4 + t) * 4 + tig;
                *dst = bf2u(acc[t][rr * 2 + 0] * f, acc[t][rr * 2 + 1] * f);
            }
        }
    }
    __syncthreads();

    {
        unsigned atBase = sbase;
        unsigned vBase = sbase + VS_U * 4;
        float av[6][4];
#pragma unroll
        for (int t = 0; t < 6; ++t)
#pragma unroll
            for (int q = 0; q < 4; ++q) av[t][q] = 0.f;
#pragma unroll
        for (int ks = 0; ks < 4; ++ks) {
            unsigned a[4];
            lda_frag(a, atBase, mt * 16, ks * 32, 144, lane);
            unsigned vrow = vBase + (ks * 16 + (lane & 15)) * 208;
#pragma unroll
            for (int t = 0; t < 6; ++t) {
                int ch0 = (nhalf * 6 + t) * 8;
                unsigned b0, b1;
                ldsm_x2t(b0, b1, vrow + ch0 * 2);
                mma16(av[t], a, b0, b1);
            }
        }
#pragma unroll
        for (int t = 0; t < 6; ++t) {
            int ch = (nhalf * 6 + t) * 8 + 2 * tig;
#pragma unroll
            for (int rr = 0; rr < 2; ++rr) {
                int r = mt * 16 + g + rr * 8;
                if (r < 49) {
                    *reinterpret_cast<unsigned*>(&g_ctx[(size_t)tok_s[r] * 96 + ch]) =
                        bf2u(av[t][rr * 2 + 0], av[t][rr * 2 + 1]);
                }
            }
        }
    }
}

// ---------------------------------------------------------------------------
extern "C" void kernel_launch(void* const* d_in, const int* in_sizes, int n_in,
                              void* d_out, int out_size) {
    const float* x    = (const float*)d_in[0];
    const float* n1w  = (const float*)d_in[1];
    const float* n1b  = (const float*)d_in[2];
    const float* qkvw = (const float*)d_in[3];
    const float* qkvb = (const float*)d_in[4];
    const float* rel  = (const float*)d_in[5];
    const float* pw   = (const float*)d_in[6];
    const float* pb   = (const float*)d_in[7];
    const float* n2w  = (const float*)d_in[8];
    const float* n2b  = (const float*)d_in[9];
    const float* w1   = (const float*)d_in[10];
    const float* b1   = (const float*)d_in[11];
    const float* w2   = (const float*)d_in[12];
    const float* b2   = (const float*)d_in[13];
    float* out = (float*)d_out;

    void *p_ctx;
    cudaGetSymbolAddress(&p_ctx, g_ctx);

    const int SMQKV  = QKV_SMEM_U * 4;    // 59392
    const int SMPML  = PML_SMEM_U * 4;    // 171008
    const int SMATTN = SM_ATTN_U * 4;     // 44848

    cudaFuncSetAttribute(k_qkv,  cudaFuncAttributeMaxDynamicSharedMemorySize, SMQKV);
    cudaFuncSetAttribute(k_pml,  cudaFuncAttributeMaxDynamicSharedMemorySize, SMPML);
    cudaFuncSetAttribute(k_attn, cudaFuncAttributeMaxDynamicSharedMemorySize, SMATTN);

    k_prep<<<436, 256>>>(qkvw, pw, w1, w2, rel);
    k_qkv<<<6272, 256, SMQKV>>>(x, n1w, n1b, qkvb);
    k_attn<<<NWIN, 256, SMATTN>>>();
    k_pml<<<3136, 512, SMPML>>>(
        (const __nv_bfloat16*)p_ctx, pb, x, n2w, n2b, b1, b2, out);
}

// round 16
// speedup vs baseline: 1.0393x; 1.0393x over previous
#include <cuda_runtime.h>
#include <cuda_bf16.h>
#include <math.h>

#define HW 50176              // 224*224
#define L_TOK 401408          // 8*224*224
#define NWIN 8192

// Scratch
__device__ __nv_bfloat16 g_qkv[(size_t)L_TOK * 288];
__device__ __nv_bfloat16 g_ctx[(size_t)L_TOK * 96];
// bf16 weights
__device__ __nv_bfloat16 g_bwq[288 * 96];
__device__ __nv_bfloat16 g_bwp[96 * 96];
__device__ __nv_bfloat16 g_bw1[384 * 96];
__device__ __nv_bfloat16 g_bw2[96 * 384];
// combined rel-pos bias + shift-mask tables, 4 classes, [49][50] bf16
__device__ __nv_bfloat16 g_tbl[4 * 2456];

// ---- helpers --------------------------------------------------------------
__device__ __forceinline__ unsigned bf2u(float a, float b) {
    __nv_bfloat162 h = __floats2bfloat162_rn(a, b);
    return *reinterpret_cast<unsigned*>(&h);
}
__device__ __forceinline__ void mma16(float* c, const unsigned* a,
                                      unsigned b0, unsigned b1) {
    asm("mma.sync.aligned.m16n8k16.row.col.f32.bf16.bf16.f32 "
        "{%0,%1,%2,%3}, {%4,%5,%6,%7}, {%8,%9}, {%0,%1,%2,%3};"
        : "+f"(c[0]), "+f"(c[1]), "+f"(c[2]), "+f"(c[3])
        : "r"(a[0]), "r"(a[1]), "r"(a[2]), "r"(a[3]), "r"(b0), "r"(b1));
}
__device__ __forceinline__ unsigned s2u(const void* p) {
    return (unsigned)__cvta_generic_to_shared(p);
}
__device__ __forceinline__ void cp16(unsigned dst, const void* src) {
    asm volatile("cp.async.cg.shared.global [%0], [%1], 16;" :: "r"(dst), "l"(src));
}
#define CP_COMMIT() asm volatile("cp.async.commit_group;")
#define CP_WAIT0()  asm volatile("cp.async.wait_group 0;")
#define CP_WAIT1()  asm volatile("cp.async.wait_group 1;")

__device__ __forceinline__ void ldsm_x4(unsigned& r0, unsigned& r1,
                                        unsigned& r2, unsigned& r3, unsigned addr) {
    asm volatile("ldmatrix.sync.aligned.m8n8.x4.shared.b16 {%0,%1,%2,%3}, [%4];"
                 : "=r"(r0), "=r"(r1), "=r"(r2), "=r"(r3) : "r"(addr));
}
__device__ __forceinline__ void ldsm_x2(unsigned& r0, unsigned& r1, unsigned addr) {
    asm volatile("ldmatrix.sync.aligned.m8n8.x2.shared.b16 {%0,%1}, [%2];"
                 : "=r"(r0), "=r"(r1) : "r"(addr));
}
__device__ __forceinline__ void ldsm_x2t(unsigned& r0, unsigned& r1, unsigned addr) {
    asm volatile("ldmatrix.sync.aligned.m8n8.x2.trans.shared.b16 {%0,%1}, [%2];"
                 : "=r"(r0), "=r"(r1) : "r"(addr));
}
__device__ __forceinline__ void lda_frag(unsigned* a, unsigned baseB, int r0,
                                         int ksB, int strideB, int lane) {
    unsigned addr = baseB + (unsigned)((r0 + (lane & 15)) * strideB + ksB + (lane >> 4) * 16);
    ldsm_x4(a[0], a[1], a[2], a[3], addr);
}
__device__ __forceinline__ void ldb_frag(unsigned& b0, unsigned& b1, unsigned baseB,
                                         int cb, int ksB, int strideB, int lane) {
    unsigned addr = baseB + (unsigned)((cb + (lane & 7)) * strideB + ksB + ((lane >> 3) & 1) * 16);
    ldsm_x2(b0, b1, addr);
}
// fast GELU: 0.5x(1+tanh(0.79788456x + 0.03567741x^3)) with tanh.approx
__device__ __forceinline__ float gelu_f(float x) {
    float x2 = x * x;
    float z = x * (0.7978845608028654f + 0.0356774081f * x2);
    float t;
    asm("tanh.approx.f32 %0, %1;" : "=f"(t) : "f"(z));
    return 0.5f * x * (1.0f + t);
}

// ---------------------------------------------------------------------------
// Kernel 0: weights fp32 -> bf16 AND bias+mask class tables (merged)
// ---------------------------------------------------------------------------
__global__ __launch_bounds__(256) void k_prep(const float* __restrict__ qkvw,
                                              const float* __restrict__ pw,
                                              const float* __restrict__ w1,
                                              const float* __restrict__ w2,
                                              const float* __restrict__ rel) {
    int b = blockIdx.x;
    if (b < 432) {
        int i = b * 256 + threadIdx.x;
        if (i < 27648)       g_bwq[i] = __float2bfloat16(qkvw[i]);
        else if (i < 36864)  g_bwp[i - 27648] = __float2bfloat16(pw[i - 27648]);
        else if (i < 73728)  g_bw1[i - 36864] = __float2bfloat16(w1[i - 36864]);
        else                 g_bw2[i - 73728] = __float2bfloat16(w2[i - 73728]);
    } else {
        int cls = b - 432;
        int re = cls >> 1, ce = cls & 1;
        for (int e = threadIdx.x; e < 2456; e += 256) {
            int i = e / 50, j = e % 50;
            float v = 0.f;
            if (i < 49 && j < 49) {
                int idx = (i / 7 - j / 7 + 6) * 13 + (i % 7 - j % 7 + 6);
                v = rel[idx];
                int li = (re ? ((i / 7) < 4 ? 1 : 2) : 0) * 3 + (ce ? ((i % 7) < 4 ? 1 : 2) : 0);
                int lj = (re ? ((j / 7) < 4 ? 1 : 2) : 0) * 3 + (ce ? ((j % 7) < 4 ? 1 : 2) : 0);
                if (li != lj) v -= 100.f;
            }
            g_tbl[cls * 2456 + e] = __float2bfloat16(v);
        }
    }
}

// ---------------------------------------------------------------------------
// Kernel 1: fused NCHW load + LN1 + QKV GEMM.  BM=64. (frozen)
// ---------------------------------------------------------------------------
#define QKV_XS 0
#define QKV_AS 6528
#define QKV_W0 9856
#define QKV_SMEM_U 14848

__global__ __launch_bounds__(256) void k_qkv(const float* __restrict__ x,
                                             const float* __restrict__ lnw,
                                             const float* __restrict__ lnb,
                                             const float* __restrict__ bias) {
    extern __shared__ unsigned smem_u[];
    int tid = threadIdx.x;
    int lane = tid & 31, warp = tid >> 5;
    int warp_m = warp & 1, warp_n = warp >> 1;
    int g = lane >> 2, tig = lane & 3;
    int m0 = blockIdx.x * 64;
    int bb = m0 / HW, hw0 = m0 % HW;

    unsigned sbase = s2u(smem_u);
#pragma unroll
    for (int l = 0; l < 6; ++l) {
        int o = tid + l * 256;
        int ch = o >> 4, t4 = o & 15;
        cp16(sbase + (QKV_XS + ch * 68 + t4 * 4) * 4,
             x + ((size_t)bb * 96 + ch) * HW + hw0 + t4 * 4);
    }
#pragma unroll
    for (int l = 0; l < 5; ++l) {
        int o = tid + l * 256;
        if (o < 1152) {
            int row = o / 12, ch = o % 12;
            cp16(sbase + QKV_W0 * 4 + row * 208 + ch * 16, g_bwq + (size_t)row * 96 + ch * 8);
        }
    }
    CP_COMMIT();
    CP_WAIT0();
    __syncthreads();

    // LN1: 4 threads per token (all 256 threads)
    {
        const float* xs = reinterpret_cast<const float*>(smem_u + QKV_XS);
        int r = tid >> 2, quarter = tid & 3;
        float vals[24];
        float s = 0.f, q = 0.f;
#pragma unroll
        for (int i = 0; i < 24; ++i) {
            float v = xs[(quarter * 24 + i) * 68 + r];
            vals[i] = v;
            s += v; q += v * v;
        }
        s += __shfl_xor_sync(0xffffffffu, s, 1);
        q += __shfl_xor_sync(0xffffffffu, q, 1);
        s += __shfl_xor_sync(0xffffffffu, s, 2);
        q += __shfl_xor_sync(0xffffffffu, q, 2);
        float mean = s * (1.f / 96.f);
        float var = q * (1.f / 96.f) - mean * mean;
        float rstd = rsqrtf(var + 1e-5f);
        unsigned* As = smem_u + QKV_AS;
#pragma unroll
        for (int i = 0; i < 12; ++i) {
            int c = quarter * 24 + i * 2;
            As[r * 52 + c / 2] = bf2u((vals[i * 2] - mean) * rstd * lnw[c] + lnb[c],
                                      (vals[i * 2 + 1] - mean) * rstd * lnw[c + 1] + lnb[c + 1]);
        }
    }
    __syncthreads();   // LN done; XS dead -> slotB (@0) writable

    // prefetch W block 1 -> slotB
#pragma unroll
    for (int l = 0; l < 5; ++l) {
        int o = tid + l * 256;
        if (o < 1152) {
            int row = o / 12, ch = o % 12;
            cp16(sbase + 0 + row * 208 + ch * 16, g_bwq + (size_t)(96 + row) * 96 + ch * 8);
        }
    }
    CP_COMMIT();

    unsigned aBase = sbase + QKV_AS * 4;
    __nv_bfloat16* out = g_qkv;

    auto gemm_block = [&](unsigned bBase, int nb) {
        float acc[2][3][4];
#pragma unroll
        for (int mt = 0; mt < 2; ++mt)
#pragma unroll
            for (int nt = 0; nt < 3; ++nt)
#pragma unroll
                for (int q = 0; q < 4; ++q) acc[mt][nt][q] = 0.f;
#pragma unroll
        for (int ks = 0; ks < 6; ++ks) {
            unsigned a[2][4];
#pragma unroll
            for (int mt = 0; mt < 2; ++mt)
                lda_frag(a[mt], aBase, warp_m * 32 + mt * 16, ks * 32, 208, lane);
#pragma unroll
            for (int nt = 0; nt < 3; ++nt) {
                unsigned b0, b1;
                ldb_frag(b0, b1, bBase, warp_n * 24 + nt * 8, ks * 32, 208, lane);
#pragma unroll
                for (int mt = 0; mt < 2; ++mt)
                    mma16(acc[mt][nt], a[mt], b0, b1);
            }
        }
        float sc = (nb == 0) ? 0.10206207261596575f : 1.0f;
#pragma unroll
        for (int mt = 0; mt < 2; ++mt) {
            int r0 = m0 + warp_m * 32 + mt * 16 + g;
#pragma unroll
            for (int nt = 0; nt < 3; ++nt) {
                int col = nb * 96 + warp_n * 24 + nt * 8 + 2 * tig;
                float bi0 = bias[col], bi1 = bias[col + 1];
                *reinterpret_cast<unsigned*>(&out[(size_t)r0 * 288 + col]) =
                    bf2u((acc[mt][nt][0] + bi0) * sc, (acc[mt][nt][1] + bi1) * sc);
                *reinterpret_cast<unsigned*>(&out[(size_t)(r0 + 8) * 288 + col]) =
                    bf2u((acc[mt][nt][2] + bi0) * sc, (acc[mt][nt][3] + bi1) * sc);
            }
        }
    };

    gemm_block(sbase + QKV_W0 * 4, 0);
    __syncthreads();
#pragma unroll
    for (int l = 0; l < 5; ++l) {
        int o = tid + l * 256;
        if (o < 1152) {
            int row = o / 12, ch = o % 12;
            cp16(sbase + QKV_W0 * 4 + row * 208 + ch * 16,
                 g_bwq + (size_t)(192 + row) * 96 + ch * 8);
        }
    }
    CP_COMMIT();
    CP_WAIT1();
    __syncthreads();
    gemm_block(sbase + 0, 1);
    CP_WAIT0();
    __syncthreads();
    gemm_block(sbase + QKV_W0 * 4, 2);
}

// ---------------------------------------------------------------------------
// Fused proj + x-residual + LN2 + MLP1 + GELU + MLP2 + residual + NCHW out.
// R14 shape: BM=64, 256 threads, full-M buffer, double-buffered weights.
// smem (u32): A@0 (3328), S0@3328, S1@8320 (4992 ea), M/XR@13312 (12544),
//             EX@25856 (1024). Total 26880u = 107520B.
// ---------------------------------------------------------------------------
#define PML_S0 3328
#define PML_S1 8320
#define PML_M  13312
#define PML_EX 25856
#define PML_SMEM_U 26880

__global__ __launch_bounds__(256) void k_pml(const __nv_bfloat16* __restrict__ A,
                                             const float* __restrict__ pbias,
                                             const float* __restrict__ x,
                                             const float* __restrict__ lnw,
                                             const float* __restrict__ lnb,
                                             const float* __restrict__ b1,
                                             const float* __restrict__ b2,
                                             float* __restrict__ out) {
    extern __shared__ unsigned smem_u[];
    int tid = threadIdx.x;
    int lane = tid & 31, warp = tid >> 5;
    int warp_m = warp & 1, warp_n = warp >> 1;
    int g = lane >> 2, tig = lane & 3;
    int m0 = blockIdx.x * 64;
    int bb = m0 / HW, hw0 = m0 % HW;

    unsigned sbase = s2u(smem_u);
    // G1: ctx A-tile + proj W -> S0
#pragma unroll
    for (int l = 0; l < 3; ++l) {
        int o = tid + l * 256;
        int row = o / 12, ch = o % 12;
        cp16(sbase + row * 208 + ch * 16, A + (size_t)(m0 + row) * 96 + ch * 8);
    }
#pragma unroll
    for (int l = 0; l < 5; ++l) {
        int o = tid + l * 256;
        if (o < 1152) {
            int row = o / 12, ch = o % 12;
            cp16(sbase + PML_S0 * 4 + row * 208 + ch * 16, g_bwp + (size_t)row * 96 + ch * 8);
        }
    }
    CP_COMMIT();
    // G2: W1 block 0 -> S1, x residual tile -> XR (overlay on M region)
#pragma unroll
    for (int l = 0; l < 5; ++l) {
        int o = tid + l * 256;
        if (o < 1152) {
            int row = o / 12, ch = o % 12;
            cp16(sbase + PML_S1 * 4 + row * 208 + ch * 16, g_bw1 + (size_t)row * 96 + ch * 8);
        }
    }
#pragma unroll
    for (int l = 0; l < 6; ++l) {
        int o = tid + l * 256;
        int ch = o >> 4, t4 = o & 15;
        cp16(sbase + (PML_M + ch * 68 + t4 * 4) * 4,
             x + ((size_t)bb * 96 + ch) * HW + hw0 + t4 * 4);
    }
    CP_COMMIT();
    CP_WAIT1();
    __syncthreads();

    // ---- proj GEMM -> h ----------------------------------------------------
    float h[2][3][4];
#pragma unroll
    for (int mt = 0; mt < 2; ++mt)
#pragma unroll
        for (int nt = 0; nt < 3; ++nt)
#pragma unroll
            for (int q = 0; q < 4; ++q) h[mt][nt][q] = 0.f;
#pragma unroll
    for (int ks = 0; ks < 6; ++ks) {
        unsigned a[2][4];
#pragma unroll
        for (int mt = 0; mt < 2; ++mt)
            lda_frag(a[mt], sbase, warp_m * 32 + mt * 16, ks * 32, 208, lane);
#pragma unroll
        for (int nt = 0; nt < 3; ++nt) {
            unsigned b0, b1;
            ldb_frag(b0, b1, sbase + PML_S0 * 4, warp_n * 24 + nt * 8, ks * 32, 208, lane);
#pragma unroll
            for (int mt = 0; mt < 2; ++mt)
                mma16(h[mt][nt], a[mt], b0, b1);
        }
    }
    CP_WAIT0();        // XR (and W1b0) ready
    __syncthreads();
    // epilogue: + proj bias + x residual from XR smem
    {
        const float* xr = reinterpret_cast<const float*>(smem_u + PML_M);
#pragma unroll
        for (int mt = 0; mt < 2; ++mt) {
            int r0 = warp_m * 32 + mt * 16 + g;
#pragma unroll
            for (int nt = 0; nt < 3; ++nt) {
                int col = warp_n * 24 + nt * 8 + 2 * tig;
                h[mt][nt][0] += pbias[col]     + xr[col * 68 + r0];
                h[mt][nt][1] += pbias[col + 1] + xr[(col + 1) * 68 + r0];
                h[mt][nt][2] += pbias[col]     + xr[col * 68 + r0 + 8];
                h[mt][nt][3] += pbias[col + 1] + xr[(col + 1) * 68 + r0 + 8];
            }
        }
    }
    // ---- LN2: register partials + smem exchange ---------------------------
    float ps[2][2], pq[2][2];
#pragma unroll
    for (int mt = 0; mt < 2; ++mt)
#pragma unroll
        for (int rr = 0; rr < 2; ++rr) {
            float s = 0.f, q = 0.f;
#pragma unroll
            for (int nt = 0; nt < 3; ++nt) {
                s += h[mt][nt][rr * 2 + 0] + h[mt][nt][rr * 2 + 1];
                q += h[mt][nt][rr * 2 + 0] * h[mt][nt][rr * 2 + 0] +
                     h[mt][nt][rr * 2 + 1] * h[mt][nt][rr * 2 + 1];
            }
            s += __shfl_xor_sync(0xffffffffu, s, 1);
            q += __shfl_xor_sync(0xffffffffu, q, 1);
            s += __shfl_xor_sync(0xffffffffu, s, 2);
            q += __shfl_xor_sync(0xffffffffu, q, 2);
            ps[mt][rr] = s; pq[mt][rr] = q;
        }
    __syncthreads();   // XR reads done
    {
        float2* ex = reinterpret_cast<float2*>(smem_u + PML_EX);
        if (tig == 0) {
#pragma unroll
            for (int mt = 0; mt < 2; ++mt)
#pragma unroll
                for (int rr = 0; rr < 2; ++rr) {
                    int row = warp_m * 32 + mt * 16 + g + rr * 8;
                    ex[row * 4 + warp_n] = make_float2(ps[mt][rr], pq[mt][rr]);
                }
        }
    }
    __syncthreads();
    {
        const float2* ex = reinterpret_cast<const float2*>(smem_u + PML_EX);
        unsigned* As = smem_u;   // ln2 bf16 tile overlays ctx
#pragma unroll
        for (int mt = 0; mt < 2; ++mt)
#pragma unroll
            for (int rr = 0; rr < 2; ++rr) {
                int row = warp_m * 32 + mt * 16 + g + rr * 8;
                float2 e0 = ex[row * 4 + 0], e1 = ex[row * 4 + 1];
                float2 e2 = ex[row * 4 + 2], e3 = ex[row * 4 + 3];
                float s = e0.x + e1.x + e2.x + e3.x;
                float q = e0.y + e1.y + e2.y + e3.y;
                float mean = s * (1.f / 96.f);
                float var = q * (1.f / 96.f) - mean * mean;
                float rstd = rsqrtf(var + 1e-5f);
#pragma unroll
                for (int nt = 0; nt < 3; ++nt) {
                    int col = warp_n * 24 + nt * 8 + 2 * tig;
                    float v0 = (h[mt][nt][rr * 2 + 0] - mean) * rstd * lnw[col] + lnb[col];
                    float v1 = (h[mt][nt][rr * 2 + 1] - mean) * rstd * lnw[col + 1] + lnb[col + 1];
                    As[row * 52 + col / 2] = bf2u(v0, v1);
                }
            }
    }
    // NOTE: no barrier here — the MLP1 loop's first-iteration
    // CP_WAIT0 + __syncthreads provides the ln2-tile visibility.

    unsigned* MU = smem_u + PML_M;
    const unsigned wslot[2] = {PML_S1, PML_S0};

    // ---- MLP1: 4 N-blocks + GELU -> M smem --------------------------------
    for (int nb = 0; nb < 4; ++nb) {
        CP_WAIT0();
        __syncthreads();
        {
            const __nv_bfloat16* nsrc = (nb < 3)
                ? g_bw1 + (size_t)(nb + 1) * 96 * 96
                : g_bw2;
            unsigned dslot = wslot[(nb + 1) & 1];
#pragma unroll
            for (int l = 0; l < 5; ++l) {
                int o = tid + l * 256;
                if (o < 1152) {
                    int row = o / 12, ch = o % 12;
                    if (nb < 3)
                        cp16(sbase + dslot * 4 + row * 208 + ch * 16, nsrc + (size_t)row * 96 + ch * 8);
                    else
                        cp16(sbase + dslot * 4 + row * 208 + ch * 16, nsrc + (size_t)row * 384 + ch * 8);
                }
            }
            CP_COMMIT();
        }
        unsigned bBase = sbase + wslot[nb & 1] * 4;
        float acc[2][3][4];
#pragma unroll
        for (int mt = 0; mt < 2; ++mt)
#pragma unroll
            for (int nt = 0; nt < 3; ++nt)
#pragma unroll
                for (int q = 0; q < 4; ++q) acc[mt][nt][q] = 0.f;
#pragma unroll
        for (int ks = 0; ks < 6; ++ks) {
            unsigned a[2][4];
#pragma unroll
            for (int mt = 0; mt < 2; ++mt)
                lda_frag(a[mt], sbase, warp_m * 32 + mt * 16, ks * 32, 208, lane);
#pragma unroll
            for (int nt = 0; nt < 3; ++nt) {
                unsigned b0, b1;
                ldb_frag(b0, b1, bBase, warp_n * 24 + nt * 8, ks * 32, 208, lane);
#pragma unroll
                for (int mt = 0; mt < 2; ++mt)
                    mma16(acc[mt][nt], a[mt], b0, b1);
            }
        }
#pragma unroll
        for (int mt = 0; mt < 2; ++mt) {
            int r0 = warp_m * 32 + mt * 16 + g;
#pragma unroll
            for (int nt = 0; nt < 3; ++nt) {
                int col = warp_n * 24 + nt * 8 + 2 * tig;
                float bi0 = b1[nb * 96 + col], bi1 = b1[nb * 96 + col + 1];
                float v0 = gelu_f(acc[mt][nt][0] + bi0);
                float v1 = gelu_f(acc[mt][nt][1] + bi1);
                float v2 = gelu_f(acc[mt][nt][2] + bi0);
                float v3 = gelu_f(acc[mt][nt][3] + bi1);
                MU[r0 * 196 + nb * 48 + col / 2] = bf2u(v0, v1);
                MU[(r0 + 8) * 196 + nb * 48 + col / 2] = bf2u(v2, v3);
            }
        }
    }

    // ---- MLP2: 4 K-chunks, accumulate into h -------------------------------
    for (int kc = 0; kc < 4; ++kc) {
        CP_WAIT0();
        __syncthreads();
        if (kc < 3) {
            unsigned dslot = wslot[(kc + 1) & 1];
#pragma unroll
            for (int l = 0; l < 5; ++l) {
                int o = tid + l * 256;
                if (o < 1152) {
                    int row = o / 12, ch = o % 12;
                    cp16(sbase + dslot * 4 + row * 208 + ch * 16,
                         g_bw2 + (size_t)row * 384 + (kc + 1) * 96 + ch * 8);
                }
            }
            CP_COMMIT();
        }
        unsigned bBase = sbase + wslot[kc & 1] * 4;
        unsigned mBase = sbase + PML_M * 4 + kc * 192;
#pragma unroll
        for (int ks = 0; ks < 6; ++ks) {
            unsigned a[2][4];
#pragma unroll
            for (int mt = 0; mt < 2; ++mt)
                lda_frag(a[mt], mBase, warp_m * 32 + mt * 16, ks * 32, 784, lane);
#pragma unroll
            for (int nt = 0; nt < 3; ++nt) {
                unsigned b0, b1;
                ldb_frag(b0, b1, bBase, warp_n * 24 + nt * 8, ks * 32, 208, lane);
#pragma unroll
                for (int mt = 0; mt < 2; ++mt)
                    mma16(h[mt][nt], a[mt], b0, b1);
            }
        }
    }

    // ---- epilogue: +b2, NCHW store -----------------------------------------
    __syncthreads();
    float (*st)[98] = reinterpret_cast<float (*)[98]>(smem_u + PML_M);
#pragma unroll
    for (int mt = 0; mt < 2; ++mt) {
        int lr0 = warp_m * 32 + mt * 16 + g;
#pragma unroll
        for (int nt = 0; nt < 3; ++nt) {
            int col = warp_n * 24 + nt * 8 + 2 * tig;
            float bi0 = b2[col], bi1 = b2[col + 1];
            *reinterpret_cast<float2*>(&st[lr0][col]) =
                make_float2(h[mt][nt][0] + bi0, h[mt][nt][1] + bi1);
            *reinterpret_cast<float2*>(&st[lr0 + 8][col]) =
                make_float2(h[mt][nt][2] + bi0, h[mt][nt][3] + bi1);
        }
    }
    __syncthreads();
    float* ob = out + (size_t)bb * 96 * HW + hw0;
#pragma unroll
    for (int l = 0; l < 24; ++l) {
        int e = tid + l * 256;
        int ch = e >> 6, tok = e & 63;
        ob[(size_t)ch * HW + tok] = st[tok][ch];
    }
}

// ---------------------------------------------------------------------------
// Attention, register softmax; Q arrives pre-scaled. (frozen)
// ---------------------------------------------------------------------------
#define QS_U 0
#define KS_U 3328
#define VS_U 6656
#define TB_U 9984
#define EX_U 3328
#define SM_ATTN_U 11212

__global__ __launch_bounds__(256) void k_attn() {
    extern __shared__ unsigned smem_u[];
    __shared__ int tok_s[49];

    int win = blockIdx.x;
    int bb = win >> 10;
    int wr = (win >> 5) & 31;
    int wc = win & 31;
    int tid = threadIdx.x;
    int lane = tid & 31, warp = tid >> 5;
    int g = lane >> 2, tig = lane & 3;
    int mt = warp & 3, nhalf = warp >> 2;
    int cls = ((wr == 31) ? 2 : 0) + ((wc == 31) ? 1 : 0);

    if (tid < 49) {
        int i = tid / 7, j = tid % 7;
        int sr = wr * 7 + i, sc = wc * 7 + j;
        int r = sr + 3; if (r >= 224) r -= 224;
        int c = sc + 3; if (c >= 224) c -= 224;
        tok_s[tid] = bb * HW + r * 224 + c;
    }
    for (int e = tid; e < 780; e += 256) smem_u[VS_U + 49 * 52 + e] = 0u;
    __syncthreads();

    unsigned sbase = s2u(smem_u);
#pragma unroll
    for (int l = 0; l < 7; ++l) {
        int e = tid + l * 256;
        if (e < 1764) {
            int third = e / 588;
            int ee = e - third * 588;
            int row = ee / 12, ch = ee % 12;
            cp16(sbase + third * 13312 + row * 208 + ch * 16,
                 g_qkv + (size_t)tok_s[row] * 288 + third * 96 + ch * 8);
        }
    }
    {
        const __nv_bfloat16* tsrc = g_tbl + cls * 2456;
        for (int o = tid; o < 307; o += 256)
            cp16(sbase + TB_U * 4 + o * 16, tsrc + o * 8);
    }
    CP_COMMIT();
    CP_WAIT0();
    __syncthreads();

    float acc[4][4];
#pragma unroll
    for (int t = 0; t < 4; ++t)
#pragma unroll
        for (int q = 0; q < 4; ++q) acc[t][q] = 0.f;
#pragma unroll
    for (int ks = 0; ks < 6; ++ks) {
        unsigned a[4];
        lda_frag(a, sbase, mt * 16, ks * 32, 208, lane);
#pragma unroll
        for (int t = 0; t < 4; ++t) {
            unsigned b0, b1;
            ldb_frag(b0, b1, sbase + KS_U * 4, (nhalf * 4 + t) * 8, ks * 32, 208, lane);
            mma16(acc[t], a, b0, b1);
        }
    }

    const __nv_bfloat16* tb = reinterpret_cast<const __nv_bfloat16*>(smem_u + TB_U);
    float mx[2] = {-1e30f, -1e30f};
#pragma unroll
    for (int t = 0; t < 4; ++t) {
        int j0 = (nhalf * 4 + t) * 8 + 2 * tig;
#pragma unroll
        for (int rr = 0; rr < 2; ++rr) {
            int i = mt * 16 + g + rr * 8;
            float v0 = acc[t][rr * 2 + 0];
            float v1 = acc[t][rr * 2 + 1];
            if (i < 49 && j0 < 49) {
                __nv_bfloat162 t2 = *reinterpret_cast<const __nv_bfloat162*>(&tb[i * 50 + j0]);
                v0 += __bfloat162float(t2.x);
                v1 += __bfloat162float(t2.y);
            }
            if (j0 > 48) v0 = -1e30f;
            if (j0 + 1 > 48) v1 = -1e30f;
            acc[t][rr * 2 + 0] = v0;
            acc[t][rr * 2 + 1] = v1;
            mx[rr] = fmaxf(mx[rr], fmaxf(v0, v1));
        }
    }
#pragma unroll
    for (int rr = 0; rr < 2; ++rr) {
        mx[rr] = fmaxf(mx[rr], __shfl_xor_sync(0xffffffffu, mx[rr], 1));
        mx[rr] = fmaxf(mx[rr], __shfl_xor_sync(0xffffffffu, mx[rr], 2));
    }
    float sm[2] = {0.f, 0.f};
#pragma unroll
    for (int t = 0; t < 4; ++t)
#pragma unroll
        for (int rr = 0; rr < 2; ++rr) {
            float p0 = __expf(acc[t][rr * 2 + 0] - mx[rr]);
            float p1 = __expf(acc[t][rr * 2 + 1] - mx[rr]);
            acc[t][rr * 2 + 0] = p0;
            acc[t][rr * 2 + 1] = p1;
            sm[rr] += p0 + p1;
        }
#pragma unroll
    for (int rr = 0; rr < 2; ++rr) {
        sm[rr] += __shfl_xor_sync(0xffffffffu, sm[rr], 1);
        sm[rr] += __shfl_xor_sync(0xffffffffu, sm[rr], 2);
    }

    __syncthreads();
    {
        float2* ex = reinterpret_cast<float2*>(smem_u + EX_U);
        if (tig == 0) {
#pragma unroll
            for (int rr = 0; rr < 2; ++rr) {
                int i = mt * 16 + g + rr * 8;
                ex[i * 2 + nhalf] = make_float2(mx[rr], sm[rr]);
            }
        }
    }
    __syncthreads();
    {
        const float2* ex = reinterpret_cast<const float2*>(smem_u + EX_U);
        __nv_bfloat16* atth = reinterpret_cast<__nv_bfloat16*>(smem_u + QS_U);
#pragma unroll
        for (int rr = 0; rr < 2; ++rr) {
            int i = mt * 16 + g + rr * 8;
            float2 e0 = ex[i * 2 + 0];
            float2 e1 = ex[i * 2 + 1];
            float M = fmaxf(e0.x, e1.x);
            float S = e0.y * __expf(e0.x - M) + e1.y * __expf(e1.x - M);
            float f = __expf(mx[rr] - M) / S;
#pragma unroll
            for (int t = 0; t < 4; ++t) {
                unsigned* dst = reinterpret_cast<unsigned*>(atth) +
                                i * 36 + (nhalf * 4 + t) * 4 + tig;
                *dst = bf2u(acc[t][rr * 2 + 0] * f, acc[t][rr * 2 + 1] * f);
            }
        }
    }
    __syncthreads();

    {
        unsigned atBase = sbase;
        unsigned vBase = sbase + VS_U * 4;
        float av[6][4];
#pragma unroll
        for (int t = 0; t < 6; ++t)
#pragma unroll
            for (int q = 0; q < 4; ++q) av[t][q] = 0.f;
#pragma unroll
        for (int ks = 0; ks < 4; ++ks) {
            unsigned a[4];
            lda_frag(a, atBase, mt * 16, ks * 32, 144, lane);
            unsigned vrow = vBase + (ks * 16 + (lane & 15)) * 208;
#pragma unroll
            for (int t = 0; t < 6; ++t) {
                int ch0 = (nhalf * 6 + t) * 8;
                unsigned b0, b1;
                ldsm_x2t(b0, b1, vrow + ch0 * 2);
                mma16(av[t], a, b0, b1);
            }
        }
#pragma unroll
        for (int t = 0; t < 6; ++t) {
            int ch = (nhalf * 6 + t) * 8 + 2 * tig;
#pragma unroll
            for (int rr = 0; rr < 2; ++rr) {
                int r = mt * 16 + g + rr * 8;
                if (r < 49) {
                    *reinterpret_cast<unsigned*>(&g_ctx[(size_t)tok_s[r] * 96 + ch]) =
                        bf2u(av[t][rr * 2 + 0], av[t][rr * 2 + 1]);
                }
            }
        }
    }
}

// ---------------------------------------------------------------------------
extern "C" void kernel_launch(void* const* d_in, const int* in_sizes, int n_in,
                              void* d_out, int out_size) {
    const float* x    = (const float*)d_in[0];
    const float* n1w  = (const float*)d_in[1];
    const float* n1b  = (const float*)d_in[2];
    const float* qkvw = (const float*)d_in[3];
    const float* qkvb = (const float*)d_in[4];
    const float* rel  = (const float*)d_in[5];
    const float* pw   = (const float*)d_in[6];
    const float* pb   = (const float*)d_in[7];
    const float* n2w  = (const float*)d_in[8];
    const float* n2b  = (const float*)d_in[9];
    const float* w1   = (const float*)d_in[10];
    const float* b1   = (const float*)d_in[11];
    const float* w2   = (const float*)d_in[12];
    const float* b2   = (const float*)d_in[13];
    float* out = (float*)d_out;

    void *p_ctx;
    cudaGetSymbolAddress(&p_ctx, g_ctx);

    const int SMQKV  = QKV_SMEM_U * 4;    // 59392
    const int SMPML  = PML_SMEM_U * 4;    // 107520
    const int SMATTN = SM_ATTN_U * 4;     // 44848

    cudaFuncSetAttribute(k_qkv,  cudaFuncAttributeMaxDynamicSharedMemorySize, SMQKV);
    cudaFuncSetAttribute(k_pml,  cudaFuncAttributeMaxDynamicSharedMemorySize, SMPML);
    cudaFuncSetAttribute(k_attn, cudaFuncAttributeMaxDynamicSharedMemorySize, SMATTN);

    k_prep<<<436, 256>>>(qkvw, pw, w1, w2, rel);
    k_qkv<<<6272, 256, SMQKV>>>(x, n1w, n1b, qkvb);
    k_attn<<<NWIN, 256, SMATTN>>>();
    k_pml<<<6272, 256, SMPML>>>(
        (const __nv_bfloat16*)p_ctx, pb, x, n2w, n2b, b1, b2, out);
}

// round 17
// speedup vs baseline: 1.0702x; 1.0298x over previous
#include <cuda_runtime.h>
#include <cuda_bf16.h>
#include <math.h>

#define HW 50176              // 224*224
#define L_TOK 401408          // 8*224*224
#define NWIN 8192

// Scratch
__device__ __nv_bfloat16 g_qkv[(size_t)L_TOK * 288];
__device__ __nv_bfloat16 g_ctx[(size_t)L_TOK * 96];
// bf16 weights
__device__ __nv_bfloat16 g_bwq[288 * 96];
__device__ __nv_bfloat16 g_bwp[96 * 96];
__device__ __nv_bfloat16 g_bw1[384 * 96];
__device__ __nv_bfloat16 g_bw2[96 * 384];
// combined rel-pos bias + shift-mask tables, 4 classes, [49][50] bf16
__device__ __nv_bfloat16 g_tbl[4 * 2456];

// ---- helpers --------------------------------------------------------------
__device__ __forceinline__ unsigned bf2u(float a, float b) {
    __nv_bfloat162 h = __floats2bfloat162_rn(a, b);
    return *reinterpret_cast<unsigned*>(&h);
}
__device__ __forceinline__ void mma16(float* c, const unsigned* a,
                                      unsigned b0, unsigned b1) {
    asm("mma.sync.aligned.m16n8k16.row.col.f32.bf16.bf16.f32 "
        "{%0,%1,%2,%3}, {%4,%5,%6,%7}, {%8,%9}, {%0,%1,%2,%3};"
        : "+f"(c[0]), "+f"(c[1]), "+f"(c[2]), "+f"(c[3])
        : "r"(a[0]), "r"(a[1]), "r"(a[2]), "r"(a[3]), "r"(b0), "r"(b1));
}
__device__ __forceinline__ unsigned s2u(const void* p) {
    return (unsigned)__cvta_generic_to_shared(p);
}
__device__ __forceinline__ void cp16(unsigned dst, const void* src) {
    asm volatile("cp.async.cg.shared.global [%0], [%1], 16;" :: "r"(dst), "l"(src));
}
#define CP_COMMIT() asm volatile("cp.async.commit_group;")
#define CP_WAIT0()  asm volatile("cp.async.wait_group 0;")
#define CP_WAIT1()  asm volatile("cp.async.wait_group 1;")

__device__ __forceinline__ void ldsm_x4(unsigned& r0, unsigned& r1,
                                        unsigned& r2, unsigned& r3, unsigned addr) {
    asm volatile("ldmatrix.sync.aligned.m8n8.x4.shared.b16 {%0,%1,%2,%3}, [%4];"
                 : "=r"(r0), "=r"(r1), "=r"(r2), "=r"(r3) : "r"(addr));
}
__device__ __forceinline__ void ldsm_x2(unsigned& r0, unsigned& r1, unsigned addr) {
    asm volatile("ldmatrix.sync.aligned.m8n8.x2.shared.b16 {%0,%1}, [%2];"
                 : "=r"(r0), "=r"(r1) : "r"(addr));
}
__device__ __forceinline__ void ldsm_x2t(unsigned& r0, unsigned& r1, unsigned addr) {
    asm volatile("ldmatrix.sync.aligned.m8n8.x2.trans.shared.b16 {%0,%1}, [%2];"
                 : "=r"(r0), "=r"(r1) : "r"(addr));
}
__device__ __forceinline__ void lda_frag(unsigned* a, unsigned baseB, int r0,
                                         int ksB, int strideB, int lane) {
    unsigned addr = baseB + (unsigned)((r0 + (lane & 15)) * strideB + ksB + (lane >> 4) * 16);
    ldsm_x4(a[0], a[1], a[2], a[3], addr);
}
__device__ __forceinline__ void ldb_frag(unsigned& b0, unsigned& b1, unsigned baseB,
                                         int cb, int ksB, int strideB, int lane) {
    unsigned addr = baseB + (unsigned)((cb + (lane & 7)) * strideB + ksB + ((lane >> 3) & 1) * 16);
    ldsm_x2(b0, b1, addr);
}
// paired B fragments: two adjacent 8-row n-blocks (cb, cb+8), one ldmatrix.x4.
// r0,r1 = fragment for rows cb..cb+7; r2,r3 = rows cb+8..cb+15.
__device__ __forceinline__ void ldb2_frag(unsigned* b, unsigned baseB,
                                          int cb, int ksB, int strideB, int lane) {
    unsigned addr = baseB + (unsigned)((cb + (lane & 7) + ((lane >> 4) & 1) * 8) * strideB
                                       + ksB + ((lane >> 3) & 1) * 16);
    ldsm_x4(b[0], b[1], b[2], b[3], addr);
}
// fast GELU: 0.5x(1+tanh(0.79788456x + 0.03567741x^3)) with tanh.approx
__device__ __forceinline__ float gelu_f(float x) {
    float x2 = x * x;
    float z = x * (0.7978845608028654f + 0.0356774081f * x2);
    float t;
    asm("tanh.approx.f32 %0, %1;" : "=f"(t) : "f"(z));
    return 0.5f * x * (1.0f + t);
}

// ---------------------------------------------------------------------------
// Kernel 0: weights fp32 -> bf16 AND bias+mask class tables (merged)
// ---------------------------------------------------------------------------
__global__ __launch_bounds__(256) void k_prep(const float* __restrict__ qkvw,
                                              const float* __restrict__ pw,
                                              const float* __restrict__ w1,
                                              const float* __restrict__ w2,
                                              const float* __restrict__ rel) {
    int b = blockIdx.x;
    if (b < 432) {
        int i = b * 256 + threadIdx.x;
        if (i < 27648)       g_bwq[i] = __float2bfloat16(qkvw[i]);
        else if (i < 36864)  g_bwp[i - 27648] = __float2bfloat16(pw[i - 27648]);
        else if (i < 73728)  g_bw1[i - 36864] = __float2bfloat16(w1[i - 36864]);
        else                 g_bw2[i - 73728] = __float2bfloat16(w2[i - 73728]);
    } else {
        int cls = b - 432;
        int re = cls >> 1, ce = cls & 1;
        for (int e = threadIdx.x; e < 2456; e += 256) {
            int i = e / 50, j = e % 50;
            float v = 0.f;
            if (i < 49 && j < 49) {
                int idx = (i / 7 - j / 7 + 6) * 13 + (i % 7 - j % 7 + 6);
                v = rel[idx];
                int li = (re ? ((i / 7) < 4 ? 1 : 2) : 0) * 3 + (ce ? ((i % 7) < 4 ? 1 : 2) : 0);
                int lj = (re ? ((j / 7) < 4 ? 1 : 2) : 0) * 3 + (ce ? ((j % 7) < 4 ? 1 : 2) : 0);
                if (li != lj) v -= 100.f;
            }
            g_tbl[cls * 2456 + e] = __float2bfloat16(v);
        }
    }
}

// ---------------------------------------------------------------------------
// Kernel 1: fused NCHW load + LN1 + QKV GEMM.  BM=64.
// ---------------------------------------------------------------------------
#define QKV_XS 0
#define QKV_AS 6528
#define QKV_W0 9856
#define QKV_SMEM_U 14848

__global__ __launch_bounds__(256) void k_qkv(const float* __restrict__ x,
                                             const float* __restrict__ lnw,
                                             const float* __restrict__ lnb,
                                             const float* __restrict__ bias) {
    extern __shared__ unsigned smem_u[];
    int tid = threadIdx.x;
    int lane = tid & 31, warp = tid >> 5;
    int warp_m = warp & 1, warp_n = warp >> 1;
    int g = lane >> 2, tig = lane & 3;
    int m0 = blockIdx.x * 64;
    int bb = m0 / HW, hw0 = m0 % HW;

    unsigned sbase = s2u(smem_u);
#pragma unroll
    for (int l = 0; l < 6; ++l) {
        int o = tid + l * 256;
        int ch = o >> 4, t4 = o & 15;
        cp16(sbase + (QKV_XS + ch * 68 + t4 * 4) * 4,
             x + ((size_t)bb * 96 + ch) * HW + hw0 + t4 * 4);
    }
#pragma unroll
    for (int l = 0; l < 5; ++l) {
        int o = tid + l * 256;
        if (o < 1152) {
            int row = o / 12, ch = o % 12;
            cp16(sbase + QKV_W0 * 4 + row * 208 + ch * 16, g_bwq + (size_t)row * 96 + ch * 8);
        }
    }
    CP_COMMIT();
    CP_WAIT0();
    __syncthreads();

    // LN1: 4 threads per token (all 256 threads)
    {
        const float* xs = reinterpret_cast<const float*>(smem_u + QKV_XS);
        int r = tid >> 2, quarter = tid & 3;
        float vals[24];
        float s = 0.f, q = 0.f;
#pragma unroll
        for (int i = 0; i < 24; ++i) {
            float v = xs[(quarter * 24 + i) * 68 + r];
            vals[i] = v;
            s += v; q += v * v;
        }
        s += __shfl_xor_sync(0xffffffffu, s, 1);
        q += __shfl_xor_sync(0xffffffffu, q, 1);
        s += __shfl_xor_sync(0xffffffffu, s, 2);
        q += __shfl_xor_sync(0xffffffffu, q, 2);
        float mean = s * (1.f / 96.f);
        float var = q * (1.f / 96.f) - mean * mean;
        float rstd = rsqrtf(var + 1e-5f);
        unsigned* As = smem_u + QKV_AS;
#pragma unroll
        for (int i = 0; i < 12; ++i) {
            int c = quarter * 24 + i * 2;
            As[r * 52 + c / 2] = bf2u((vals[i * 2] - mean) * rstd * lnw[c] + lnb[c],
                                      (vals[i * 2 + 1] - mean) * rstd * lnw[c + 1] + lnb[c + 1]);
        }
    }
    __syncthreads();   // LN done; XS dead -> slotB (@0) writable

    // prefetch W block 1 -> slotB
#pragma unroll
    for (int l = 0; l < 5; ++l) {
        int o = tid + l * 256;
        if (o < 1152) {
            int row = o / 12, ch = o % 12;
            cp16(sbase + 0 + row * 208 + ch * 16, g_bwq + (size_t)(96 + row) * 96 + ch * 8);
        }
    }
    CP_COMMIT();

    unsigned aBase = sbase + QKV_AS * 4;
    __nv_bfloat16* out = g_qkv;

    auto gemm_block = [&](unsigned bBase, int nb) {
        float acc[2][3][4];
#pragma unroll
        for (int mt = 0; mt < 2; ++mt)
#pragma unroll
            for (int nt = 0; nt < 3; ++nt)
#pragma unroll
                for (int q = 0; q < 4; ++q) acc[mt][nt][q] = 0.f;
#pragma unroll
        for (int ks = 0; ks < 6; ++ks) {
            unsigned a[2][4];
#pragma unroll
            for (int mt = 0; mt < 2; ++mt)
                lda_frag(a[mt], aBase, warp_m * 32 + mt * 16, ks * 32, 208, lane);
            unsigned b[6];
            ldb2_frag(b, bBase, warp_n * 24, ks * 32, 208, lane);
            ldb_frag(b[4], b[5], bBase, warp_n * 24 + 16, ks * 32, 208, lane);
#pragma unroll
            for (int nt = 0; nt < 3; ++nt)
#pragma unroll
                for (int mt = 0; mt < 2; ++mt)
                    mma16(acc[mt][nt], a[mt], b[nt * 2], b[nt * 2 + 1]);
        }
        float sc = (nb == 0) ? 0.10206207261596575f : 1.0f;
#pragma unroll
        for (int mt = 0; mt < 2; ++mt) {
            int r0 = m0 + warp_m * 32 + mt * 16 + g;
#pragma unroll
            for (int nt = 0; nt < 3; ++nt) {
                int col = nb * 96 + warp_n * 24 + nt * 8 + 2 * tig;
                float bi0 = bias[col], bi1 = bias[col + 1];
                *reinterpret_cast<unsigned*>(&out[(size_t)r0 * 288 + col]) =
                    bf2u((acc[mt][nt][0] + bi0) * sc, (acc[mt][nt][1] + bi1) * sc);
                *reinterpret_cast<unsigned*>(&out[(size_t)(r0 + 8) * 288 + col]) =
                    bf2u((acc[mt][nt][2] + bi0) * sc, (acc[mt][nt][3] + bi1) * sc);
            }
        }
    };

    gemm_block(sbase + QKV_W0 * 4, 0);
    __syncthreads();
#pragma unroll
    for (int l = 0; l < 5; ++l) {
        int o = tid + l * 256;
        if (o < 1152) {
            int row = o / 12, ch = o % 12;
            cp16(sbase + QKV_W0 * 4 + row * 208 + ch * 16,
                 g_bwq + (size_t)(192 + row) * 96 + ch * 8);
        }
    }
    CP_COMMIT();
    CP_WAIT1();
    __syncthreads();
    gemm_block(sbase + 0, 1);
    CP_WAIT0();
    __syncthreads();
    gemm_block(sbase + QKV_W0 * 4, 2);
}

// ---------------------------------------------------------------------------
// Fused proj + x-residual + LN2 + MLP1 + GELU + MLP2 + residual + NCHW out.
// R14 shape: BM=64, 256 threads, full-M buffer, double-buffered weights.
// ---------------------------------------------------------------------------
#define PML_S0 3328
#define PML_S1 8320
#define PML_M  13312
#define PML_EX 25856
#define PML_SMEM_U 26880

__global__ __launch_bounds__(256) void k_pml(const __nv_bfloat16* __restrict__ A,
                                             const float* __restrict__ pbias,
                                             const float* __restrict__ x,
                                             const float* __restrict__ lnw,
                                             const float* __restrict__ lnb,
                                             const float* __restrict__ b1,
                                             const float* __restrict__ b2,
                                             float* __restrict__ out) {
    extern __shared__ unsigned smem_u[];
    int tid = threadIdx.x;
    int lane = tid & 31, warp = tid >> 5;
    int warp_m = warp & 1, warp_n = warp >> 1;
    int g = lane >> 2, tig = lane & 3;
    int m0 = blockIdx.x * 64;
    int bb = m0 / HW, hw0 = m0 % HW;

    unsigned sbase = s2u(smem_u);
    // G1: ctx A-tile + proj W -> S0
#pragma unroll
    for (int l = 0; l < 3; ++l) {
        int o = tid + l * 256;
        int row = o / 12, ch = o % 12;
        cp16(sbase + row * 208 + ch * 16, A + (size_t)(m0 + row) * 96 + ch * 8);
    }
#pragma unroll
    for (int l = 0; l < 5; ++l) {
        int o = tid + l * 256;
        if (o < 1152) {
            int row = o / 12, ch = o % 12;
            cp16(sbase + PML_S0 * 4 + row * 208 + ch * 16, g_bwp + (size_t)row * 96 + ch * 8);
        }
    }
    CP_COMMIT();
    // G2: W1 block 0 -> S1, x residual tile -> XR (overlay on M region)
#pragma unroll
    for (int l = 0; l < 5; ++l) {
        int o = tid + l * 256;
        if (o < 1152) {
            int row = o / 12, ch = o % 12;
            cp16(sbase + PML_S1 * 4 + row * 208 + ch * 16, g_bw1 + (size_t)row * 96 + ch * 8);
        }
    }
#pragma unroll
    for (int l = 0; l < 6; ++l) {
        int o = tid + l * 256;
        int ch = o >> 4, t4 = o & 15;
        cp16(sbase + (PML_M + ch * 68 + t4 * 4) * 4,
             x + ((size_t)bb * 96 + ch) * HW + hw0 + t4 * 4);
    }
    CP_COMMIT();
    CP_WAIT1();
    __syncthreads();

    // ---- proj GEMM -> h ----------------------------------------------------
    float h[2][3][4];
#pragma unroll
    for (int mt = 0; mt < 2; ++mt)
#pragma unroll
        for (int nt = 0; nt < 3; ++nt)
#pragma unroll
            for (int q = 0; q < 4; ++q) h[mt][nt][q] = 0.f;
#pragma unroll
    for (int ks = 0; ks < 6; ++ks) {
        unsigned a[2][4];
#pragma unroll
        for (int mt = 0; mt < 2; ++mt)
            lda_frag(a[mt], sbase, warp_m * 32 + mt * 16, ks * 32, 208, lane);
        unsigned b[6];
        ldb2_frag(b, sbase + PML_S0 * 4, warp_n * 24, ks * 32, 208, lane);
        ldb_frag(b[4], b[5], sbase + PML_S0 * 4, warp_n * 24 + 16, ks * 32, 208, lane);
#pragma unroll
        for (int nt = 0; nt < 3; ++nt)
#pragma unroll
            for (int mt = 0; mt < 2; ++mt)
                mma16(h[mt][nt], a[mt], b[nt * 2], b[nt * 2 + 1]);
    }
    CP_WAIT0();        // XR (and W1b0) ready
    __syncthreads();
    // epilogue: + proj bias + x residual from XR smem
    {
        const float* xr = reinterpret_cast<const float*>(smem_u + PML_M);
#pragma unroll
        for (int mt = 0; mt < 2; ++mt) {
            int r0 = warp_m * 32 + mt * 16 + g;
#pragma unroll
            for (int nt = 0; nt < 3; ++nt) {
                int col = warp_n * 24 + nt * 8 + 2 * tig;
                h[mt][nt][0] += pbias[col]     + xr[col * 68 + r0];
                h[mt][nt][1] += pbias[col + 1] + xr[(col + 1) * 68 + r0];
                h[mt][nt][2] += pbias[col]     + xr[col * 68 + r0 + 8];
                h[mt][nt][3] += pbias[col + 1] + xr[(col + 1) * 68 + r0 + 8];
            }
        }
    }
    // ---- LN2: register partials + smem exchange ---------------------------
    float ps[2][2], pq[2][2];
#pragma unroll
    for (int mt = 0; mt < 2; ++mt)
#pragma unroll
        for (int rr = 0; rr < 2; ++rr) {
            float s = 0.f, q = 0.f;
#pragma unroll
            for (int nt = 0; nt < 3; ++nt) {
                s += h[mt][nt][rr * 2 + 0] + h[mt][nt][rr * 2 + 1];
                q += h[mt][nt][rr * 2 + 0] * h[mt][nt][rr * 2 + 0] +
                     h[mt][nt][rr * 2 + 1] * h[mt][nt][rr * 2 + 1];
            }
            s += __shfl_xor_sync(0xffffffffu, s, 1);
            q += __shfl_xor_sync(0xffffffffu, q, 1);
            s += __shfl_xor_sync(0xffffffffu, s, 2);
            q += __shfl_xor_sync(0xffffffffu, q, 2);
            ps[mt][rr] = s; pq[mt][rr] = q;
        }
    __syncthreads();   // XR reads done
    {
        float2* ex = reinterpret_cast<float2*>(smem_u + PML_EX);
        if (tig == 0) {
#pragma unroll
            for (int mt = 0; mt < 2; ++mt)
#pragma unroll
                for (int rr = 0; rr < 2; ++rr) {
                    int row = warp_m * 32 + mt * 16 + g + rr * 8;
                    ex[row * 4 + warp_n] = make_float2(ps[mt][rr], pq[mt][rr]);
                }
        }
    }
    __syncthreads();
    {
        const float2* ex = reinterpret_cast<const float2*>(smem_u + PML_EX);
        unsigned* As = smem_u;   // ln2 bf16 tile overlays ctx
#pragma unroll
        for (int mt = 0; mt < 2; ++mt)
#pragma unroll
            for (int rr = 0; rr < 2; ++rr) {
                int row = warp_m * 32 + mt * 16 + g + rr * 8;
                float2 e0 = ex[row * 4 + 0], e1 = ex[row * 4 + 1];
                float2 e2 = ex[row * 4 + 2], e3 = ex[row * 4 + 3];
                float s = e0.x + e1.x + e2.x + e3.x;
                float q = e0.y + e1.y + e2.y + e3.y;
                float mean = s * (1.f / 96.f);
                float var = q * (1.f / 96.f) - mean * mean;
                float rstd = rsqrtf(var + 1e-5f);
#pragma unroll
                for (int nt = 0; nt < 3; ++nt) {
                    int col = warp_n * 24 + nt * 8 + 2 * tig;
                    float v0 = (h[mt][nt][rr * 2 + 0] - mean) * rstd * lnw[col] + lnb[col];
                    float v1 = (h[mt][nt][rr * 2 + 1] - mean) * rstd * lnw[col + 1] + lnb[col + 1];
                    As[row * 52 + col / 2] = bf2u(v0, v1);
                }
            }
    }
    // NOTE: no barrier here — the MLP1 loop's first-iteration
    // CP_WAIT0 + __syncthreads provides the ln2-tile visibility.

    unsigned* MU = smem_u + PML_M;
    const unsigned wslot[2] = {PML_S1, PML_S0};

    // ---- MLP1: 4 N-blocks + GELU -> M smem --------------------------------
    for (int nb = 0; nb < 4; ++nb) {
        CP_WAIT0();
        __syncthreads();
        {
            const __nv_bfloat16* nsrc = (nb < 3)
                ? g_bw1 + (size_t)(nb + 1) * 96 * 96
                : g_bw2;
            unsigned dslot = wslot[(nb + 1) & 1];
#pragma unroll
            for (int l = 0; l < 5; ++l) {
                int o = tid + l * 256;
                if (o < 1152) {
                    int row = o / 12, ch = o % 12;
                    if (nb < 3)
                        cp16(sbase + dslot * 4 + row * 208 + ch * 16, nsrc + (size_t)row * 96 + ch * 8);
                    else
                        cp16(sbase + dslot * 4 + row * 208 + ch * 16, nsrc + (size_t)row * 384 + ch * 8);
                }
            }
            CP_COMMIT();
        }
        unsigned bBase = sbase + wslot[nb & 1] * 4;
        float acc[2][3][4];
#pragma unroll
        for (int mt = 0; mt < 2; ++mt)
#pragma unroll
            for (int nt = 0; nt < 3; ++nt)
#pragma unroll
                for (int q = 0; q < 4; ++q) acc[mt][nt][q] = 0.f;
#pragma unroll
        for (int ks = 0; ks < 6; ++ks) {
            unsigned a[2][4];
#pragma unroll
            for (int mt = 0; mt < 2; ++mt)
                lda_frag(a[mt], sbase, warp_m * 32 + mt * 16, ks * 32, 208, lane);
            unsigned b[6];
            ldb2_frag(b, bBase, warp_n * 24, ks * 32, 208, lane);
            ldb_frag(b[4], b[5], bBase, warp_n * 24 + 16, ks * 32, 208, lane);
#pragma unroll
            for (int nt = 0; nt < 3; ++nt)
#pragma unroll
                for (int mt = 0; mt < 2; ++mt)
                    mma16(acc[mt][nt], a[mt], b[nt * 2], b[nt * 2 + 1]);
        }
#pragma unroll
        for (int mt = 0; mt < 2; ++mt) {
            int r0 = warp_m * 32 + mt * 16 + g;
#pragma unroll
            for (int nt = 0; nt < 3; ++nt) {
                int col = warp_n * 24 + nt * 8 + 2 * tig;
                float bi0 = b1[nb * 96 + col], bi1 = b1[nb * 96 + col + 1];
                float v0 = gelu_f(acc[mt][nt][0] + bi0);
                float v1 = gelu_f(acc[mt][nt][1] + bi1);
                float v2 = gelu_f(acc[mt][nt][2] + bi0);
                float v3 = gelu_f(acc[mt][nt][3] + bi1);
                MU[r0 * 196 + nb * 48 + col / 2] = bf2u(v0, v1);
                MU[(r0 + 8) * 196 + nb * 48 + col / 2] = bf2u(v2, v3);
            }
        }
    }

    // ---- MLP2: 4 K-chunks, accumulate into h -------------------------------
    for (int kc = 0; kc < 4; ++kc) {
        CP_WAIT0();
        __syncthreads();
        if (kc < 3) {
            unsigned dslot = wslot[(kc + 1) & 1];
#pragma unroll
            for (int l = 0; l < 5; ++l) {
                int o = tid + l * 256;
                if (o < 1152) {
                    int row = o / 12, ch = o % 12;
                    cp16(sbase + dslot * 4 + row * 208 + ch * 16,
                         g_bw2 + (size_t)row * 384 + (kc + 1) * 96 + ch * 8);
                }
            }
            CP_COMMIT();
        }
        unsigned bBase = sbase + wslot[kc & 1] * 4;
        unsigned mBase = sbase + PML_M * 4 + kc * 192;
#pragma unroll
        for (int ks = 0; ks < 6; ++ks) {
            unsigned a[2][4];
#pragma unroll
            for (int mt = 0; mt < 2; ++mt)
                lda_frag(a[mt], mBase, warp_m * 32 + mt * 16, ks * 32, 784, lane);
            unsigned b[6];
            ldb2_frag(b, bBase, warp_n * 24, ks * 32, 208, lane);
            ldb_frag(b[4], b[5], bBase, warp_n * 24 + 16, ks * 32, 208, lane);
#pragma unroll
            for (int nt = 0; nt < 3; ++nt)
#pragma unroll
                for (int mt = 0; mt < 2; ++mt)
                    mma16(h[mt][nt], a[mt], b[nt * 2], b[nt * 2 + 1]);
        }
    }

    // ---- epilogue: +b2, NCHW store -----------------------------------------
    __syncthreads();
    float (*st)[98] = reinterpret_cast<float (*)[98]>(smem_u + PML_M);
#pragma unroll
    for (int mt = 0; mt < 2; ++mt) {
        int lr0 = warp_m * 32 + mt * 16 + g;
#pragma unroll
        for (int nt = 0; nt < 3; ++nt) {
            int col = warp_n * 24 + nt * 8 + 2 * tig;
            float bi0 = b2[col], bi1 = b2[col + 1];
            *reinterpret_cast<float2*>(&st[lr0][col]) =
                make_float2(h[mt][nt][0] + bi0, h[mt][nt][1] + bi1);
            *reinterpret_cast<float2*>(&st[lr0 + 8][col]) =
                make_float2(h[mt][nt][2] + bi0, h[mt][nt][3] + bi1);
        }
    }
    __syncthreads();
    float* ob = out + (size_t)bb * 96 * HW + hw0;
#pragma unroll
    for (int l = 0; l < 24; ++l) {
        int e = tid + l * 256;
        int ch = e >> 6, tok = e & 63;
        ob[(size_t)ch * HW + tok] = st[tok][ch];
    }
}

// ---------------------------------------------------------------------------
// Attention, register softmax; Q arrives pre-scaled.
// ---------------------------------------------------------------------------
#define QS_U 0
#define KS_U 3328
#define VS_U 6656
#define TB_U 9984
#define EX_U 3328
#define SM_ATTN_U 11212

__global__ __launch_bounds__(256) void k_attn() {
    extern __shared__ unsigned smem_u[];
    __shared__ int tok_s[49];

    int win = blockIdx.x;
    int bb = win >> 10;
    int wr = (win >> 5) & 31;
    int wc = win & 31;
    int tid = threadIdx.x;
    int lane = tid & 31, warp = tid >> 5;
    int g = lane >> 2, tig = lane & 3;
    int mt = warp & 3, nhalf = warp >> 2;
    int cls = ((wr == 31) ? 2 : 0) + ((wc == 31) ? 1 : 0);

    if (tid < 49) {
        int i = tid / 7, j = tid % 7;
        int sr = wr * 7 + i, sc = wc * 7 + j;
        int r = sr + 3; if (r >= 224) r -= 224;
        int c = sc + 3; if (c >= 224) c -= 224;
        tok_s[tid] = bb * HW + r * 224 + c;
    }
    for (int e = tid; e < 780; e += 256) smem_u[VS_U + 49 * 52 + e] = 0u;
    __syncthreads();

    unsigned sbase = s2u(smem_u);
#pragma unroll
    for (int l = 0; l < 7; ++l) {
        int e = tid + l * 256;
        if (e < 1764) {
            int third = e / 588;
            int ee = e - third * 588;
            int row = ee / 12, ch = ee % 12;
            cp16(sbase + third * 13312 + row * 208 + ch * 16,
                 g_qkv + (size_t)tok_s[row] * 288 + third * 96 + ch * 8);
        }
    }
    {
        const __nv_bfloat16* tsrc = g_tbl + cls * 2456;
        for (int o = tid; o < 307; o += 256)
            cp16(sbase + TB_U * 4 + o * 16, tsrc + o * 8);
    }
    CP_COMMIT();
    CP_WAIT0();
    __syncthreads();

    float acc[4][4];
#pragma unroll
    for (int t = 0; t < 4; ++t)
#pragma unroll
        for (int q = 0; q < 4; ++q) acc[t][q] = 0.f;
#pragma unroll
    for (int ks = 0; ks < 6; ++ks) {
        unsigned a[4];
        lda_frag(a, sbase, mt * 16, ks * 32, 208, lane);
        unsigned b[8];
        ldb2_frag(b,     sbase + KS_U * 4, nhalf * 32,      ks * 32, 208, lane);
        ldb2_frag(b + 4, sbase + KS_U * 4, nhalf * 32 + 16, ks * 32, 208, lane);
#pragma unroll
        for (int t = 0; t < 4; ++t)
            mma16(acc[t], a, b[t * 2], b[t * 2 + 1]);
    }

    const __nv_bfloat16* tb = reinterpret_cast<const __nv_bfloat16*>(smem_u + TB_U);
    float mx[2] = {-1e30f, -1e30f};
#pragma unroll
    for (int t = 0; t < 4; ++t) {
        int j0 = (nhalf * 4 + t) * 8 + 2 * tig;
#pragma unroll
        for (int rr = 0; rr < 2; ++rr) {
            int i = mt * 16 + g + rr * 8;
            float v0 = acc[t][rr * 2 + 0];
            float v1 = acc[t][rr * 2 + 1];
            if (i < 49 && j0 < 49) {
                __nv_bfloat162 t2 = *reinterpret_cast<const __nv_bfloat162*>(&tb[i * 50 + j0]);
                v0 += __bfloat162float(t2.x);
                v1 += __bfloat162float(t2.y);
            }
            if (j0 > 48) v0 = -1e30f;
            if (j0 + 1 > 48) v1 = -1e30f;
            acc[t][rr * 2 + 0] = v0;
            acc[t][rr * 2 + 1] = v1;
            mx[rr] = fmaxf(mx[rr], fmaxf(v0, v1));
        }
    }
#pragma unroll
    for (int rr = 0; rr < 2; ++rr) {
        mx[rr] = fmaxf(mx[rr], __shfl_xor_sync(0xffffffffu, mx[rr], 1));
        mx[rr] = fmaxf(mx[rr], __shfl_xor_sync(0xffffffffu, mx[rr], 2));
    }
    float sm[2] = {0.f, 0.f};
#pragma unroll
    for (int t = 0; t < 4; ++t)
#pragma unroll
        for (int rr = 0; rr < 2; ++rr) {
            float p0 = __expf(acc[t][rr * 2 + 0] - mx[rr]);
            float p1 = __expf(acc[t][rr * 2 + 1] - mx[rr]);
            acc[t][rr * 2 + 0] = p0;
            acc[t][rr * 2 + 1] = p1;
            sm[rr] += p0 + p1;
        }
#pragma unroll
    for (int rr = 0; rr < 2; ++rr) {
        sm[rr] += __shfl_xor_sync(0xffffffffu, sm[rr], 1);
        sm[rr] += __shfl_xor_sync(0xffffffffu, sm[rr], 2);
    }

    __syncthreads();
    {
        float2* ex = reinterpret_cast<float2*>(smem_u + EX_U);
        if (tig == 0) {
#pragma unroll
            for (int rr = 0; rr < 2; ++rr) {
                int i = mt * 16 + g + rr * 8;
                ex[i * 2 + nhalf] = make_float2(mx[rr], sm[rr]);
            }
        }
    }
    __syncthreads();
    {
        const float2* ex = reinterpret_cast<const float2*>(smem_u + EX_U);
        __nv_bfloat16* atth = reinterpret_cast<__nv_bfloat16*>(smem_u + QS_U);
#pragma unroll
        for (int rr = 0; rr < 2; ++rr) {
            int i = mt * 16 + g + rr * 8;
            float2 e0 = ex[i * 2 + 0];
            float2 e1 = ex[i * 2 + 1];
            float M = fmaxf(e0.x, e1.x);
            float S = e0.y * __expf(e0.x - M) + e1.y * __expf(e1.x - M);
            float f = __expf(mx[rr] - M) / S;
#pragma unroll
            for (int t = 0; t < 4; ++t) {
                unsigned* dst = reinterpret_cast<unsigned*>(atth) +
                                i * 36 + (nhalf * 4 + t) * 4 + tig;
                *dst = bf2u(acc[t][rr * 2 + 0] * f, acc[t][rr * 2 + 1] * f);
            }
        }
    }
    __syncthreads();

    {
        unsigned atBase = sbase;
        unsigned vBase = sbase + VS_U * 4;
        float av[6][4];
#pragma unroll
        for (int t = 0; t < 6; ++t)
#pragma unroll
            for (int q = 0; q < 4; ++q) av[t][q] = 0.f;
#pragma unroll
        for (int ks = 0; ks < 4; ++ks) {
            unsigned a[4];
            lda_frag(a, atBase, mt * 16, ks * 32, 144, lane);
            unsigned vrow = vBase + (ks * 16 + (lane & 15)) * 208;
#pragma unroll
            for (int t = 0; t < 6; ++t) {
                int ch0 = (nhalf * 6 + t) * 8;
                unsigned b0, b1;
                ldsm_x2t(b0, b1, vrow + ch0 * 2);
                mma16(av[t], a, b0, b1);
            }
        }
#pragma unroll
        for (int t = 0; t < 6; ++t) {
            int ch = (nhalf * 6 + t) * 8 + 2 * tig;
#pragma unroll
            for (int rr = 0; rr < 2; ++rr) {
                int r = mt * 16 + g + rr * 8;
                if (r < 49) {
                    *reinterpret_cast<unsigned*>(&g_ctx[(size_t)tok_s[r] * 96 + ch]) =
                        bf2u(av[t][rr * 2 + 0], av[t][rr * 2 + 1]);
                }
            }
        }
    }
}

// ---------------------------------------------------------------------------
extern "C" void kernel_launch(void* const* d_in, const int* in_sizes, int n_in,
                              void* d_out, int out_size) {
    const float* x    = (const float*)d_in[0];
    const float* n1w  = (const float*)d_in[1];
    const float* n1b  = (const float*)d_in[2];
    const float* qkvw = (const float*)d_in[3];
    const float* qkvb = (const float*)d_in[4];
    const float* rel  = (const float*)d_in[5];
    const float* pw   = (const float*)d_in[6];
    const float* pb   = (const float*)d_in[7];
    const float* n2w  = (const float*)d_in[8];
    const float* n2b  = (const float*)d_in[9];
    const float* w1   = (const float*)d_in[10];
    const float* b1   = (const float*)d_in[11];
    const float* w2   = (const float*)d_in[12];
    const float* b2   = (const float*)d_in[13];
    float* out = (float*)d_out;

    void *p_ctx;
    cudaGetSymbolAddress(&p_ctx, g_ctx);

    const int SMQKV  = QKV_SMEM_U * 4;    // 59392
    const int SMPML  = PML_SMEM_U * 4;    // 107520
    const int SMATTN = SM_ATTN_U * 4;     // 44848

    cudaFuncSetAttribute(k_qkv,  cudaFuncAttributeMaxDynamicSharedMemorySize, SMQKV);
    cudaFuncSetAttribute(k_pml,  cudaFuncAttributeMaxDynamicSharedMemorySize, SMPML);
    cudaFuncSetAttribute(k_attn, cudaFuncAttributeMaxDynamicSharedMemorySize, SMATTN);

    k_prep<<<436, 256>>>(qkvw, pw, w1, w2, rel);
    k_qkv<<<6272, 256, SMQKV>>>(x, n1w, n1b, qkvb);
    k_attn<<<NWIN, 256, SMATTN>>>();
    k_pml<<<6272, 256, SMPML>>>(
        (const __nv_bfloat16*)p_ctx, pb, x, n2w, n2b, b1, b2, out);
}